// round 14
// baseline (speedup 1.0000x reference)
#include <cuda_runtime.h>

#define EPSV 1e-5f
#define NMAX 100000
#define EMAX 1600000
#define PB   512

typedef unsigned long long u64;

// ---------------- scratch (device globals; no allocation allowed) -------------
__device__ alignas(16) float  d_h  [NMAX * 16];
__device__ alignas(16) float  d_xl [NMAX * 32];
__device__ alignas(16) float  d_xr [NMAX * 32];
__device__ alignas(16) float  d_g  [NMAX * 32];
__device__ int       d_src [EMAX];
__device__ int       d_dst [EMAX];
__device__ alignas(16) long long d_sep[EMAX + 32]; // (eid<<32)|src permuted; padded .bss
__device__ int       d_cnt [NMAX];
__device__ int       d_off [NMAX];
__device__ int       d_cur [NMAX];
__device__ int       d_nperm[NMAX];
__device__ int       d_dcnt[1024];
__device__ int       d_dcur[1024];
__device__ int       d_bsum[256];
__device__ unsigned long long d_barc[4];
__device__ double    d_stats[4];  // [0],[1]: sum/sumsq of g; [2],[3]: of u

// ---------------- f32x2 packed helpers (sm_103a) ----------------
__device__ __forceinline__ u64 pack2(float x, float y) {
    u64 r; asm("mov.b64 %0, {%1, %2};" : "=l"(r) : "f"(x), "f"(y)); return r;
}
__device__ __forceinline__ float2 unpack2(u64 p) {
    float2 v; asm("mov.b64 {%0, %1}, %2;" : "=f"(v.x), "=f"(v.y) : "l"(p)); return v;
}
__device__ __forceinline__ u64 fma2(u64 a, u64 b, u64 c) {
    u64 r; asm("fma.rn.f32x2 %0, %1, %2, %3;" : "=l"(r) : "l"(a), "l"(b), "l"(c)); return r;
}
__device__ __forceinline__ u64 add2(u64 a, u64 b) {
    u64 r; asm("add.rn.f32x2 %0, %1, %2;" : "=l"(r) : "l"(a), "l"(b)); return r;
}
__device__ __forceinline__ u64 mul2(u64 a, u64 b) {
    u64 r; asm("mul.rn.f32x2 %0, %1, %2;" : "=l"(r) : "l"(a), "l"(b)); return r;
}
#define ABS2(a) ((a) & 0x7FFFFFFF7FFFFFFFULL)
#define K06 0x3F19999A3F19999AULL
#define K04 0x3ECCCCCD3ECCCCCDULL
__device__ __forceinline__ u64 leaky2(u64 m) { return fma2(ABS2(m), K04, mul2(m, K06)); }

__device__ __forceinline__ void gridbar(int idx, int NB) {
    __syncthreads();
    if (threadIdx.x == 0) {
        __threadfence();
        unsigned long long tk = atomicAdd(&d_barc[idx], 1ULL);
        unsigned long long target = (tk / NB + 1ULL) * (unsigned long long)NB;
        while (atomicAdd(&d_barc[idx], 0ULL) < target) { __nanosleep(64); }
    }
    __syncthreads();
}

__device__ __forceinline__ void blockReduceAdd2_256(float s, float q, double* o0, double* o1) {
    __shared__ float rs[8], rq[8];
#pragma unroll
    for (int o = 16; o; o >>= 1) {
        s += __shfl_xor_sync(0xffffffffu, s, o);
        q += __shfl_xor_sync(0xffffffffu, q, o);
    }
    int w = threadIdx.x >> 5, l = threadIdx.x & 31;
    if (l == 0) { rs[w] = s; rq[w] = q; }
    __syncthreads();
    if (w == 0) {
        s = (l < 8) ? rs[l] : 0.f;
        q = (l < 8) ? rq[l] : 0.f;
#pragma unroll
        for (int o = 4; o; o >>= 1) {
            s += __shfl_xor_sync(0xffffffffu, s, o);
            q += __shfl_xor_sync(0xffffffffu, q, o);
        }
        if (l == 0) { atomicAdd(o0, (double)s); atomicAdd(o1, (double)q); }
    }
    __syncthreads();
}

// ------- K_fused0: blocks [0,nbe): embed+LN+transform; blocks [nbe,..): hist ------
__global__ void __launch_bounds__(256) k_fused0(
    const float* __restrict__ x, const float* __restrict__ W,
    const float* __restrict__ b, const float* __restrict__ lnw,
    const float* __restrict__ lnb,
    const float* __restrict__ Wl, const float* __restrict__ bl,
    const float* __restrict__ Wr, const float* __restrict__ br,
    const int* __restrict__ ei32,
    float* __restrict__ out, int N, int E, int nbe)
{
    int t = threadIdx.x;
    if (blockIdx.x >= nbe) {
        bool is64 = true;
#pragma unroll
        for (int k = 0; k < 8; k++)
            if (__ldg(&ei32[2 * k + 1]) != 0) is64 = false;
        int i = (blockIdx.x - nbe) * 256 + t;
        if (i < 4) d_stats[i] = 0.0;
        if (i >= E) return;
        int s, d;
        if (is64) {
            const long long* e64 = (const long long*)ei32;
            s = (int)__ldcs(&e64[i]);
            d = (int)__ldcs(&e64[E + i]);
        } else {
            s = __ldcs(&ei32[i]);
            d = __ldcs(&ei32[E + i]);
        }
        s = min(max(s, 0), N - 1);
        d = min(max(d, 0), N - 1);
        d_src[i] = s;
        d_dst[i] = d;
        atomicAdd(&d_cnt[d], 1);
        return;
    }
    // ---- embed path: 16 nodes/block ----
    __shared__ float4 sx4[16 * 32];
    __shared__ float4 sWt4[32 * 16];
    __shared__ float4 sWlT[4 * 32];
    __shared__ float4 sWrT[4 * 32];
    __shared__ float4 sy4[16 * 4];
    __shared__ float  sbl[32], sbr[32];
    int n0 = blockIdx.x * 16;

    for (int i = t; i < 512; i += 256) {
        int row = i >> 5, k4 = i & 31;
        int gn = n0 + row;
        sx4[i] = (gn < N) ? __ldcs(&((const float4*)x)[gn * 32 + k4])
                          : make_float4(0.f, 0.f, 0.f, 0.f);
    }
    for (int i = t; i < 512; i += 256) {
        int k4 = i >> 4, c = i & 15;
        float4 w;
        w.x = W[(k4 * 4 + 0) * 16 + c];
        w.y = W[(k4 * 4 + 1) * 16 + c];
        w.z = W[(k4 * 4 + 2) * 16 + c];
        w.w = W[(k4 * 4 + 3) * 16 + c];
        sWt4[i] = w;
    }
    if (t < 128) {
        int k4 = t >> 5, cc = t & 31;
        float4 wl, wr;
        wl.x = Wl[(k4 * 4 + 0) * 32 + cc]; wr.x = Wr[(k4 * 4 + 0) * 32 + cc];
        wl.y = Wl[(k4 * 4 + 1) * 32 + cc]; wr.y = Wr[(k4 * 4 + 1) * 32 + cc];
        wl.z = Wl[(k4 * 4 + 2) * 32 + cc]; wr.z = Wr[(k4 * 4 + 2) * 32 + cc];
        wl.w = Wl[(k4 * 4 + 3) * 32 + cc]; wr.w = Wr[(k4 * 4 + 3) * 32 + cc];
        sWlT[t] = wl; sWrT[t] = wr;
    }
    if (t >= 128 && t < 160) { sbl[t - 128] = bl[t - 128]; sbr[t - 128] = br[t - 128]; }
    __syncthreads();

    int n = t >> 4, c = t & 15;
    int gn = n0 + n;
    float acc = b[c];
#pragma unroll
    for (int k4 = 0; k4 < 32; k4++) {
        float4 xv = sx4[n * 32 + k4];
        float4 wv = sWt4[k4 * 16 + c];
        acc += xv.x * wv.x + xv.y * wv.y + xv.z * wv.z + xv.w * wv.w;
    }
    unsigned gmask = 0xFFFFu << ((t & 31) & 16);
    float s = acc;
#pragma unroll
    for (int o = 1; o < 16; o <<= 1) s += __shfl_xor_sync(gmask, s, o);
    float mu = s * (1.f / 16.f);
    float dv = acc - mu;
    float q = dv * dv;
#pragma unroll
    for (int o = 1; o < 16; o <<= 1) q += __shfl_xor_sync(gmask, q, o);
    float inv = rsqrtf(q * (1.f / 16.f) + EPSV);
    float v = fmaxf(dv * inv * lnw[c] + lnb[c], 0.f);
    if (gn < N) { d_h[gn * 16 + c] = v; out[gn * 16 + c] = v; }
    ((float*)sy4)[n * 16 + c] = v;
    __syncthreads();

#pragma unroll
    for (int p = 0; p < 2; p++) {
        int cc = c + p * 16;
        float al = sbl[cc], ar = sbr[cc];
#pragma unroll
        for (int k4 = 0; k4 < 4; k4++) {
            float4 xv = sy4[n * 4 + k4];
            float4 wl = sWlT[k4 * 32 + cc];
            float4 wr = sWrT[k4 * 32 + cc];
            al += xv.x * wl.x + xv.y * wl.y + xv.z * wl.z + xv.w * wl.w;
            ar += xv.x * wr.x + xv.y * wr.y + xv.z * wr.z + xv.w * wr.w;
        }
        if (gn < N) {
            d_xl[gn * 32 + cc] = al;
            d_xr[gn * 32 + cc] = ar;
        }
    }
}

// ------- K_scan: edge-offset scan + degree-sort of nodes (196 blocks) -------
__global__ void __launch_bounds__(PB) k_scan(int N, int NB) {
    __shared__ int ssc[PB];
    __shared__ int sbs[256];
    __shared__ int sd[1024];
    int t = threadIdx.x, b = blockIdx.x;
    int i = b * PB + t;

    int v = (i < N) ? d_cnt[i] : 0;
    if (i < N) atomicAdd(&d_dcnt[min(v, 1023)], 1);
    ssc[t] = v;
    __syncthreads();
#pragma unroll
    for (int o = 1; o < PB; o <<= 1) {
        int u = (t >= o) ? ssc[t - o] : 0;
        __syncthreads();
        ssc[t] += u;
        __syncthreads();
    }
    int incl = ssc[t];
    if (t == PB - 1) d_bsum[b] = incl;
    gridbar(0, NB);

    if (t < 256) sbs[t] = (t < NB) ? __ldcg(&d_bsum[t]) : 0;
    __syncthreads();
#pragma unroll
    for (int o = 1; o < 256; o <<= 1) {
        int u = 0;
        if (t < 256 && t >= o) u = sbs[t - o];
        __syncthreads();
        if (t < 256) sbs[t] += u;
        __syncthreads();
    }
    int base = (b > 0) ? sbs[b - 1] : 0;
    if (i < N) {
        int off = base + incl - v;
        d_off[i] = off;
        d_cur[i] = off;
    }
    if (b == 0) {
        int v0 = __ldcg(&d_dcnt[t]), v1 = __ldcg(&d_dcnt[t + 512]);
        sd[t] = v0; sd[t + 512] = v1;
        __syncthreads();
#pragma unroll
        for (int o = 1; o < 1024; o <<= 1) {
            int a0 = (t >= o) ? sd[t - o] : 0;
            int a1 = (t + 512 >= o) ? sd[t + 512 - o] : 0;
            __syncthreads();
            sd[t] += a0; sd[t + 512] += a1;
            __syncthreads();
        }
        d_dcur[t] = sd[t] - v0;
        d_dcur[t + 512] = sd[t + 512] - v1;
    }
    gridbar(1, NB);

    // scatter nodes into DESCENDING-degree order (LPT)
    int stride = NB * PB;
    for (int n = b * PB + t; n < N; n += stride) {
        int dg = min(__ldcg(&d_cnt[n]), 1023);
        int pos = atomicAdd(&d_dcur[dg], 1);
        d_nperm[N - 1 - pos] = n;
    }
}

// ------- K_scatter: permute (src, edge-id) into dst-grouped order, 8B/edge ------
__global__ void __launch_bounds__(256) k_scatter(int E) {
    int i = blockIdx.x * 256 + threadIdx.x;
    if (i >= E) return;
    int d = d_dst[i];
    int pos = atomicAdd(&d_cur[d], 1);
    d_sep[pos] = ((long long)i << 32) | (unsigned)d_src[i];
}

// ------- K_layer: persistent per-layer kernel (196 blocks, co-resident) --------
// Phase E: per-dst attention aggregation (grid-stride, 4 lanes/node, f32x2,
//          depth-2 pipeline, LPT node order) -> stats[0,1]
// gridbar -> Phase L: graph_LN1+relu, @linW (u in regs, 2 nodes/thread) -> stats[2,3]
// gridbar -> Phase B: graph_LN2 + resid + relu -> h/out (+ next-layer xl/xr if l=0)
__global__ void __launch_bounds__(256, 2) k_layer(
    const float4* __restrict__ eattr,
    const float* __restrict__ We, const float* __restrict__ att,
    const float* __restrict__ gatb,
    const float* __restrict__ n1w, const float* __restrict__ n1b,
    const float* __restrict__ linW, const float* __restrict__ linb,
    const float* __restrict__ n2w, const float* __restrict__ n2b,
    const float* __restrict__ Wl, const float* __restrict__ bl,
    const float* __restrict__ Wr, const float* __restrict__ br,
    float* __restrict__ out, int N, int NBL, int layer)
{
    __shared__ float sWe[128];
    __shared__ float sAtt[32];
    __shared__ float sGb[32];
    __shared__ alignas(16) float sLW[512];
    __shared__ alignas(16) float sWl[512], sWr[512];
    __shared__ float sn1w[32], sn1b[32], sbl[32], sbr[32];
    __shared__ float sn2w[16], sn2b[16], slb[16];
    int t = threadIdx.x, b = blockIdx.x;

    if (layer == 1 && b == 0 && t == 255) { d_stats[2] = 0.0; d_stats[3] = 0.0; }
    if (t < 128) sWe[t] = We[t];
    else if (t < 160) sAtt[t - 128] = att[t - 128];
    else if (t < 192) sGb[t - 160] = gatb[t - 160];
    else if (t < 224) { sn1w[t - 192] = n1w[t - 192]; sn1b[t - 192] = n1b[t - 192]; }
    else if (layer == 0) { sbl[t - 224] = bl[t - 224]; sbr[t - 224] = br[t - 224]; }
    if (t < 16) { sn2w[t] = n2w[t]; sn2b[t] = n2b[t]; slb[t] = linb[t]; }
    for (int i = t; i < 512; i += 256) {
        sLW[i] = linW[i];
        if (layer == 0) { sWl[i] = Wl[i]; sWr[i] = Wr[i]; }
    }
    __syncthreads();

    // ================= Phase E: edge aggregation =================
    int lane = t & 3;
    unsigned pmask = 0x3u << ((t & 31) & ~1);
    int cb = lane * 8;
    u64 w0[4], w1[4], w2[4], w3[4], at4[4];
#pragma unroll
    for (int i = 0; i < 4; i++) {
        w0[i]  = pack2(sWe[cb + 2 * i],      sWe[cb + 2 * i + 1]);
        w1[i]  = pack2(sWe[32 + cb + 2 * i], sWe[32 + cb + 2 * i + 1]);
        w2[i]  = pack2(sWe[64 + cb + 2 * i], sWe[64 + cb + 2 * i + 1]);
        w3[i]  = pack2(sWe[96 + cb + 2 * i], sWe[96 + cb + 2 * i + 1]);
        at4[i] = pack2(sAtt[cb + 2 * i],     sAtt[cb + 2 * i + 1]);
    }
    const ulonglong2* xlu = (const ulonglong2*)d_xl;
    const ulonglong2* xru = (const ulonglong2*)d_xr;
    float s_loc = 0.f, q_loc = 0.f;

    int nstride = NBL * 64;                 // 64 nodes per block per pass
    for (int base0 = 0; base0 < N; base0 += nstride) {
        int slot = base0 + b * 64 + (t >> 2);
        if (slot >= N) break;               // uniform within warp (slots contiguous)
        int n = __ldg(&d_nperm[slot]);
        u64 xr[4], acc[4];
        {
            ulonglong2 X0 = xru[n * 8 + lane * 2];
            ulonglong2 X1 = xru[n * 8 + lane * 2 + 1];
            xr[0] = X0.x; xr[1] = X0.y; xr[2] = X1.x; xr[3] = X1.y;
        }
        float den;
        {   // self-loop (ew = 0)
            ulonglong2 A0 = xlu[n * 8 + lane * 2];
            ulonglong2 A1 = xlu[n * 8 + lane * 2 + 1];
            u64 a0 = A0.x, a1 = A0.y, a2 = A1.x, a3 = A1.y;
            u64 l0 = leaky2(add2(a0, xr[0]));
            u64 l1 = leaky2(add2(a1, xr[1]));
            u64 l2 = leaky2(add2(a2, xr[2]));
            u64 l3 = leaky2(add2(a3, xr[3]));
            u64 dd0 = fma2(l1, at4[1], mul2(l0, at4[0]));
            u64 dd1 = fma2(l3, at4[3], mul2(l2, at4[2]));
            float2 dv = unpack2(add2(dd0, dd1));
            float p = dv.x + dv.y;
            p += __shfl_xor_sync(pmask, p, 1);
            float ex = __expf(p);           // shift-free softmax
            den = ex;
            u64 e2 = pack2(ex, ex);
            acc[0] = mul2(e2, a0); acc[1] = mul2(e2, a1);
            acc[2] = mul2(e2, a2); acc[3] = mul2(e2, a3);
        }
        int start = __ldg(&d_off[n]), deg = __ldg(&d_cnt[n]);
        const long long* qp = d_sep + start;
        long long qA = __ldg(&qp[0]);
        long long qB = __ldg(&qp[1]);
        long long qC = __ldg(&qp[2]);
        int s0 = (int)qA, i0 = (int)(qA >> 32);
        int s1 = (int)qB, i1 = (int)(qB >> 32);
        ulonglong2 A0a = __ldg(&xlu[s0 * 8 + lane * 2]);
        ulonglong2 A1a = __ldg(&xlu[s0 * 8 + lane * 2 + 1]);
        float4     EAa = __ldg(&eattr[i0]);
        ulonglong2 A0b = __ldg(&xlu[s1 * 8 + lane * 2]);
        ulonglong2 A1b = __ldg(&xlu[s1 * 8 + lane * 2 + 1]);
        float4     EAb = __ldg(&eattr[i1]);
        for (int j = 0; j < deg; j++) {
            u64 a0 = A0a.x, a1 = A0a.y, a2 = A1a.x, a3 = A1a.y;
            float4 ea = EAa;
            A0a = A0b; A1a = A1b; EAa = EAb;
            int sC = (int)qC, iC = (int)(qC >> 32);
            A0b = __ldg(&xlu[sC * 8 + lane * 2]);
            A1b = __ldg(&xlu[sC * 8 + lane * 2 + 1]);
            EAb = __ldg(&eattr[iC]);
            qC = __ldg(&qp[j + 3]);
            u64 eax = pack2(ea.x, ea.x), eay = pack2(ea.y, ea.y);
            u64 eaz = pack2(ea.z, ea.z), eaw = pack2(ea.w, ea.w);
            u64 m0 = fma2(eax, w0[0], fma2(eay, w1[0], fma2(eaz, w2[0], fma2(eaw, w3[0], add2(a0, xr[0])))));
            u64 m1 = fma2(eax, w0[1], fma2(eay, w1[1], fma2(eaz, w2[1], fma2(eaw, w3[1], add2(a1, xr[1])))));
            u64 m2 = fma2(eax, w0[2], fma2(eay, w1[2], fma2(eaz, w2[2], fma2(eaw, w3[2], add2(a2, xr[2])))));
            u64 m3 = fma2(eax, w0[3], fma2(eay, w1[3], fma2(eaz, w2[3], fma2(eaw, w3[3], add2(a3, xr[3])))));
            u64 dd0 = fma2(leaky2(m1), at4[1], mul2(leaky2(m0), at4[0]));
            u64 dd1 = fma2(leaky2(m3), at4[3], mul2(leaky2(m2), at4[2]));
            float2 dv = unpack2(add2(dd0, dd1));
            float pe = dv.x + dv.y;
            pe += __shfl_xor_sync(pmask, pe, 1);
            float exe = __expf(pe);
            den += exe;
            u64 e2 = pack2(exe, exe);
            acc[0] = fma2(e2, a0, acc[0]); acc[1] = fma2(e2, a1, acc[1]);
            acc[2] = fma2(e2, a2, acc[2]); acc[3] = fma2(e2, a3, acc[3]);
        }
        float inv = 1.f / den;
        u64 inv2 = pack2(inv, inv);
        u64 r0 = fma2(acc[0], inv2, pack2(sGb[cb],     sGb[cb + 1]));
        u64 r1 = fma2(acc[1], inv2, pack2(sGb[cb + 2], sGb[cb + 3]));
        u64 r2 = fma2(acc[2], inv2, pack2(sGb[cb + 4], sGb[cb + 5]));
        u64 r3 = fma2(acc[3], inv2, pack2(sGb[cb + 6], sGb[cb + 7]));
        ulonglong2 R0; R0.x = r0; R0.y = r1;
        ulonglong2 R1; R1.x = r2; R1.y = r3;
        ((ulonglong2*)d_g)[n * 8 + lane * 2]     = R0;
        ((ulonglong2*)d_g)[n * 8 + lane * 2 + 1] = R1;
        float2 v0 = unpack2(r0), v1 = unpack2(r1), v2 = unpack2(r2), v3 = unpack2(r3);
        s_loc += (v0.x + v0.y) + (v1.x + v1.y) + (v2.x + v2.y) + (v3.x + v3.y);
        q_loc += v0.x * v0.x + v0.y * v0.y + v1.x * v1.x + v1.y * v1.y
               + v2.x * v2.x + v2.y * v2.y + v3.x * v3.x + v3.y * v3.y;
    }
    blockReduceAdd2_256(s_loc, q_loc, &d_stats[0], &d_stats[1]);
    gridbar(2, NBL);

    // ================= Phase L: lin (2 nodes/thread) =================
    u64 uu[2][8];
    float s2 = 0.f, q2 = 0.f;
    {
        double mu1d  = d_stats[0] / (32.0 * N);
        double var1d = d_stats[1] / (32.0 * N) - mu1d * mu1d;
        float mu1  = (float)mu1d;
        float inv1 = rsqrtf((float)var1d + EPSV);
#pragma unroll
        for (int p = 0; p < 2; p++) {
            int n = b * 256 + t + p * NBL * 256;
            if (n < N) {
#pragma unroll
                for (int i = 0; i < 8; i++) uu[p][i] = pack2(slb[2 * i], slb[2 * i + 1]);
                const float4* g4 = (const float4*)(d_g + n * 32);
#pragma unroll
                for (int kc = 0; kc < 4; kc++) {
                    float4 ga = __ldg(&g4[kc * 2]);
                    float4 gb = __ldg(&g4[kc * 2 + 1]);
                    float tt[8];
                    tt[0] = fmaxf((ga.x - mu1) * inv1 * sn1w[kc * 8 + 0] + sn1b[kc * 8 + 0], 0.f);
                    tt[1] = fmaxf((ga.y - mu1) * inv1 * sn1w[kc * 8 + 1] + sn1b[kc * 8 + 1], 0.f);
                    tt[2] = fmaxf((ga.z - mu1) * inv1 * sn1w[kc * 8 + 2] + sn1b[kc * 8 + 2], 0.f);
                    tt[3] = fmaxf((ga.w - mu1) * inv1 * sn1w[kc * 8 + 3] + sn1b[kc * 8 + 3], 0.f);
                    tt[4] = fmaxf((gb.x - mu1) * inv1 * sn1w[kc * 8 + 4] + sn1b[kc * 8 + 4], 0.f);
                    tt[5] = fmaxf((gb.y - mu1) * inv1 * sn1w[kc * 8 + 5] + sn1b[kc * 8 + 5], 0.f);
                    tt[6] = fmaxf((gb.z - mu1) * inv1 * sn1w[kc * 8 + 6] + sn1b[kc * 8 + 6], 0.f);
                    tt[7] = fmaxf((gb.w - mu1) * inv1 * sn1w[kc * 8 + 7] + sn1b[kc * 8 + 7], 0.f);
#pragma unroll
                    for (int kk = 0; kk < 8; kk++) {
                        int k = kc * 8 + kk;
                        u64 tk2 = pack2(tt[kk], tt[kk]);
                        const u64* wrow = (const u64*)&sLW[k * 16];
#pragma unroll
                        for (int i = 0; i < 8; i++) uu[p][i] = fma2(tk2, wrow[i], uu[p][i]);
                    }
                }
#pragma unroll
                for (int i = 0; i < 8; i++) {
                    float2 pv = unpack2(uu[p][i]);
                    s2 += pv.x + pv.y;
                    q2 += pv.x * pv.x + pv.y * pv.y;
                }
            }
        }
    }
    blockReduceAdd2_256(s2, q2, &d_stats[2], &d_stats[3]);
    gridbar(3, NBL);

    // ================= Phase B =================
    if (layer == 0 && b == 0 && t == 255) { d_stats[0] = 0.0; d_stats[1] = 0.0; }
    if (layer == 1) {   // restore zeroed counters for the next replay
        for (int i = b * 256 + t; i < N; i += NBL * 256) d_cnt[i] = 0;
        if (b < 4) d_dcnt[b * 256 + t] = 0;
    }
    double mu2d  = d_stats[2] / (16.0 * N);
    double var2d = d_stats[3] / (16.0 * N) - mu2d * mu2d;
    float mu2  = (float)mu2d;
    float inv2 = rsqrtf((float)var2d + EPSV);
#pragma unroll
    for (int p = 0; p < 2; p++) {
        int n = b * 256 + t + p * NBL * 256;
        if (n >= N) continue;
        float hn[16];
        const float4* h4 = (const float4*)(d_h + n * 16);
#pragma unroll
        for (int i = 0; i < 4; i++) {
            float4 hv = h4[i];
            float2 pa = unpack2(uu[p][i * 2]), pb = unpack2(uu[p][i * 2 + 1]);
            hn[i * 4 + 0] = fmaxf((pa.x - mu2) * inv2 * sn2w[i * 4 + 0] + sn2b[i * 4 + 0] + hv.x, 0.f);
            hn[i * 4 + 1] = fmaxf((pa.y - mu2) * inv2 * sn2w[i * 4 + 1] + sn2b[i * 4 + 1] + hv.y, 0.f);
            hn[i * 4 + 2] = fmaxf((pb.x - mu2) * inv2 * sn2w[i * 4 + 2] + sn2b[i * 4 + 2] + hv.z, 0.f);
            hn[i * 4 + 3] = fmaxf((pb.y - mu2) * inv2 * sn2w[i * 4 + 3] + sn2b[i * 4 + 3] + hv.w, 0.f);
        }
        float4* o4 = (float4*)(out + n * 16);
#pragma unroll
        for (int i = 0; i < 4; i++) {
            float4 ov = o4[i];
            ov.x = fmaxf(ov.x, hn[i * 4 + 0]);
            ov.y = fmaxf(ov.y, hn[i * 4 + 1]);
            ov.z = fmaxf(ov.z, hn[i * 4 + 2]);
            ov.w = fmaxf(ov.w, hn[i * 4 + 3]);
            o4[i] = ov;
        }
        if (layer == 0) {
            float4* hw = (float4*)(d_h + n * 16);
#pragma unroll
            for (int i = 0; i < 4; i++)
                hw[i] = make_float4(hn[i * 4], hn[i * 4 + 1], hn[i * 4 + 2], hn[i * 4 + 3]);
#pragma unroll
            for (int half = 0; half < 2; half++) {
                u64 xa[8], ra[8];
#pragma unroll
                for (int i = 0; i < 8; i++) {
                    xa[i] = pack2(sbl[half * 16 + 2 * i], sbl[half * 16 + 2 * i + 1]);
                    ra[i] = pack2(sbr[half * 16 + 2 * i], sbr[half * 16 + 2 * i + 1]);
                }
#pragma unroll
                for (int k = 0; k < 16; k++) {
                    u64 hk2 = pack2(hn[k], hn[k]);
                    const u64* wl = (const u64*)&sWl[k * 32 + half * 16];
                    const u64* wr = (const u64*)&sWr[k * 32 + half * 16];
#pragma unroll
                    for (int i = 0; i < 8; i++) {
                        xa[i] = fma2(hk2, wl[i], xa[i]);
                        ra[i] = fma2(hk2, wr[i], ra[i]);
                    }
                }
                ulonglong2* xo = (ulonglong2*)(d_xl + n * 32 + half * 16);
                ulonglong2* ro = (ulonglong2*)(d_xr + n * 32 + half * 16);
#pragma unroll
                for (int i = 0; i < 4; i++) {
                    ulonglong2 X; X.x = xa[2 * i]; X.y = xa[2 * i + 1]; xo[i] = X;
                    ulonglong2 R; R.x = ra[2 * i]; R.y = ra[2 * i + 1]; ro[i] = R;
                }
            }
        }
    }
}

// ---------------- launch ----------------
extern "C" void kernel_launch(void* const* d_in, const int* in_sizes, int n_in,
                              void* d_out, int out_size)
{
    const float* x     = (const float*)d_in[0];
    const int*   ei32  = (const int*)d_in[1];
    const float* eattr = (const float*)d_in[2];
    const float* embW  = (const float*)d_in[3];
    const float* embB  = (const float*)d_in[4];
    const float* ln0w  = (const float*)d_in[5];
    const float* ln0b  = (const float*)d_in[6];
    const float* Wl    = (const float*)d_in[7];
    const float* bl    = (const float*)d_in[8];
    const float* Wr    = (const float*)d_in[9];
    const float* br    = (const float*)d_in[10];
    const float* We    = (const float*)d_in[11];
    const float* att   = (const float*)d_in[12];
    const float* gatb  = (const float*)d_in[13];
    const float* n1w   = (const float*)d_in[14];
    const float* n1b   = (const float*)d_in[15];
    const float* linW  = (const float*)d_in[16];
    const float* linb  = (const float*)d_in[17];
    const float* n2w   = (const float*)d_in[18];
    const float* n2b   = (const float*)d_in[19];
    float* out = (float*)d_out;

    int N   = in_sizes[0] / 128;
    int E   = in_sizes[2] / 4;           // edge_attr is (E, 4)
    int NB  = (N + PB - 1) / PB;         // 196 (co-resident)
    int nbe = (N + 15) / 16;
    int nbh = (E + 255) / 256;

    k_fused0 <<<nbe + nbh, 256>>>(x, embW, embB, ln0w, ln0b,
                                  Wl, bl, Wr, br, ei32, out, N, E, nbe);   // 1
    k_scan   <<<NB, PB>>>(N, NB);                                          // 2
    k_scatter<<<(E + 255) / 256, 256>>>(E);                                // 3

    for (int l = 0; l < 2; l++) {
        k_layer<<<NB, 256>>>((const float4*)eattr,
                             We + l * 128, att + l * 32, gatb + l * 32,
                             n1w + l * 32, n1b + l * 32,
                             linW + l * 512, linb + l * 16,
                             n2w + l * 16, n2b + l * 16,
                             Wl + 512, bl + 32, Wr + 512, br + 32,
                             out, N, NB, l);                               // 4, 5
    }
}

// round 15
// speedup vs baseline: 1.1301x; 1.1301x over previous
#include <cuda_runtime.h>

#define EPSV 1e-5f
#define NMAX 100000
#define EMAX 1600000
#define PB   512

typedef unsigned long long u64;

// ---------------- scratch (device globals; no allocation allowed) -------------
__device__ alignas(16) float  d_h  [NMAX * 16];
__device__ alignas(16) float  d_xl [NMAX * 32];
__device__ alignas(16) float  d_xr [NMAX * 32];
__device__ alignas(16) float  d_g  [NMAX * 32];
__device__ int       d_src [EMAX];
__device__ int       d_dst [EMAX];
__device__ alignas(16) long long d_sep[EMAX + 32]; // (eid<<32)|src permuted; padded .bss
__device__ int       d_cnt [NMAX];
__device__ int       d_off [NMAX];
__device__ int       d_cur [NMAX];
__device__ int       d_nperm[NMAX];
__device__ int       d_dcnt[1024];
__device__ int       d_dcur[1024];
__device__ int       d_bsum[256];
__device__ unsigned long long d_barc[4];
__device__ double    d_stats[4];  // [0],[1]: sum/sumsq of g; [2],[3]: of u

// ---------------- f32x2 packed helpers (sm_103a) ----------------
__device__ __forceinline__ u64 pack2(float x, float y) {
    u64 r; asm("mov.b64 %0, {%1, %2};" : "=l"(r) : "f"(x), "f"(y)); return r;
}
__device__ __forceinline__ float2 unpack2(u64 p) {
    float2 v; asm("mov.b64 {%0, %1}, %2;" : "=f"(v.x), "=f"(v.y) : "l"(p)); return v;
}
__device__ __forceinline__ u64 fma2(u64 a, u64 b, u64 c) {
    u64 r; asm("fma.rn.f32x2 %0, %1, %2, %3;" : "=l"(r) : "l"(a), "l"(b), "l"(c)); return r;
}
__device__ __forceinline__ u64 add2(u64 a, u64 b) {
    u64 r; asm("add.rn.f32x2 %0, %1, %2;" : "=l"(r) : "l"(a), "l"(b)); return r;
}
__device__ __forceinline__ u64 mul2(u64 a, u64 b) {
    u64 r; asm("mul.rn.f32x2 %0, %1, %2;" : "=l"(r) : "l"(a), "l"(b)); return r;
}
#define ABS2(a) ((a) & 0x7FFFFFFF7FFFFFFFULL)
#define K06 0x3F19999A3F19999AULL
#define K04 0x3ECCCCCD3ECCCCCDULL
__device__ __forceinline__ u64 leaky2(u64 m) { return fma2(ABS2(m), K04, mul2(m, K06)); }

__device__ __forceinline__ void gridbar(int idx, int NB) {
    __syncthreads();
    if (threadIdx.x == 0) {
        __threadfence();
        unsigned long long tk = atomicAdd(&d_barc[idx], 1ULL);
        unsigned long long target = (tk / NB + 1ULL) * (unsigned long long)NB;
        while (atomicAdd(&d_barc[idx], 0ULL) < target) { __nanosleep(64); }
    }
    __syncthreads();
}

__device__ __forceinline__ void blockReduceAdd2_256(float s, float q, double* o0, double* o1) {
    __shared__ float rs[8], rq[8];
#pragma unroll
    for (int o = 16; o; o >>= 1) {
        s += __shfl_xor_sync(0xffffffffu, s, o);
        q += __shfl_xor_sync(0xffffffffu, q, o);
    }
    int w = threadIdx.x >> 5, l = threadIdx.x & 31;
    if (l == 0) { rs[w] = s; rq[w] = q; }
    __syncthreads();
    if (w == 0) {
        s = (l < 8) ? rs[l] : 0.f;
        q = (l < 8) ? rq[l] : 0.f;
#pragma unroll
        for (int o = 4; o; o >>= 1) {
            s += __shfl_xor_sync(0xffffffffu, s, o);
            q += __shfl_xor_sync(0xffffffffu, q, o);
        }
        if (l == 0) { atomicAdd(o0, (double)s); atomicAdd(o1, (double)q); }
    }
}

// ------- K_hist: decode edge_index + clamp + store + dst histogram + zero stats --
__global__ void __launch_bounds__(256) k_hist(const int* __restrict__ ei32, int E, int N) {
    bool is64 = true;
#pragma unroll
    for (int k = 0; k < 8; k++)
        if (__ldg(&ei32[2 * k + 1]) != 0) is64 = false;
    int i = blockIdx.x * 256 + threadIdx.x;
    if (i < 4) d_stats[i] = 0.0;
    if (i >= E) return;
    int s, d;
    if (is64) {
        const long long* e64 = (const long long*)ei32;
        s = (int)__ldcs(&e64[i]);
        d = (int)__ldcs(&e64[E + i]);
    } else {
        s = __ldcs(&ei32[i]);
        d = __ldcs(&ei32[E + i]);
    }
    s = min(max(s, 0), N - 1);
    d = min(max(d, 0), N - 1);
    d_src[i] = s;
    d_dst[i] = d;
    atomicAdd(&d_cnt[d], 1);
}

// ------- K_scan: edge-offset scan + degree-sort of nodes (196 blocks) -------
__global__ void __launch_bounds__(PB) k_scan(int N, int NB) {
    __shared__ int ssc[PB];
    __shared__ int sbs[256];
    __shared__ int sd[1024];
    int t = threadIdx.x, b = blockIdx.x;
    int i = b * PB + t;

    int v = (i < N) ? d_cnt[i] : 0;
    if (i < N) atomicAdd(&d_dcnt[min(v, 1023)], 1);
    ssc[t] = v;
    __syncthreads();
#pragma unroll
    for (int o = 1; o < PB; o <<= 1) {
        int u = (t >= o) ? ssc[t - o] : 0;
        __syncthreads();
        ssc[t] += u;
        __syncthreads();
    }
    int incl = ssc[t];
    if (t == PB - 1) d_bsum[b] = incl;
    gridbar(0, NB);

    if (t < 256) sbs[t] = (t < NB) ? __ldcg(&d_bsum[t]) : 0;
    __syncthreads();
#pragma unroll
    for (int o = 1; o < 256; o <<= 1) {
        int u = 0;
        if (t < 256 && t >= o) u = sbs[t - o];
        __syncthreads();
        if (t < 256) sbs[t] += u;
        __syncthreads();
    }
    int base = (b > 0) ? sbs[b - 1] : 0;
    if (i < N) {
        int off = base + incl - v;
        d_off[i] = off;
        d_cur[i] = off;
    }
    if (b == 0) {
        int v0 = __ldcg(&d_dcnt[t]), v1 = __ldcg(&d_dcnt[t + 512]);
        sd[t] = v0; sd[t + 512] = v1;
        __syncthreads();
#pragma unroll
        for (int o = 1; o < 1024; o <<= 1) {
            int a0 = (t >= o) ? sd[t - o] : 0;
            int a1 = (t + 512 >= o) ? sd[t + 512 - o] : 0;
            __syncthreads();
            sd[t] += a0; sd[t + 512] += a1;
            __syncthreads();
        }
        d_dcur[t] = sd[t] - v0;
        d_dcur[t + 512] = sd[t + 512] - v1;
    }
    gridbar(1, NB);

    // scatter nodes into DESCENDING-degree order (LPT)
    int stride = NB * PB;
    for (int n = b * PB + t; n < N; n += stride) {
        int dg = min(__ldcg(&d_cnt[n]), 1023);
        int pos = atomicAdd(&d_dcur[dg], 1);
        d_nperm[N - 1 - pos] = n;
    }
}

// ------- K_scatter: permute (src, edge-id) into dst-grouped order, 8B/edge ------
__global__ void __launch_bounds__(256) k_scatter(int E) {
    int i = blockIdx.x * 256 + threadIdx.x;
    if (i >= E) return;
    int d = d_dst[i];
    int pos = atomicAdd(&d_cur[d], 1);
    d_sep[pos] = ((long long)i << 32) | (unsigned)d_src[i];
}

// ------- K_embed: h = relu(node_LN(x@W+b)); out=h; xl/xr for layer 0 ------------
// 32 nodes/block (halves per-block weight reload vs 16): thread handles 2 nodes.
__global__ void __launch_bounds__(256) k_embed(
    const float* __restrict__ x, const float* __restrict__ W,
    const float* __restrict__ b, const float* __restrict__ lnw,
    const float* __restrict__ lnb,
    const float* __restrict__ Wl, const float* __restrict__ bl,
    const float* __restrict__ Wr, const float* __restrict__ br,
    float* __restrict__ out, int N)
{
    __shared__ float4 sx4[32 * 32];     // 16KB
    __shared__ float4 sWt4[32 * 16];    // 8KB: sWt4[k4*16+c] = W[k4*4+j][c]
    __shared__ float4 sWlT[4 * 32];
    __shared__ float4 sWrT[4 * 32];
    __shared__ float4 sy4[32 * 4];
    __shared__ float  sbl[32], sbr[32];
    int t = threadIdx.x;
    int n0 = blockIdx.x * 32;

    for (int i = t; i < 1024; i += 256) {
        int row = i >> 5, k4 = i & 31;
        int gn = n0 + row;
        sx4[i] = (gn < N) ? __ldcs(&((const float4*)x)[gn * 32 + k4])
                          : make_float4(0.f, 0.f, 0.f, 0.f);
    }
    for (int i = t; i < 512; i += 256) {
        int k4 = i >> 4, c = i & 15;
        float4 w;
        w.x = W[(k4 * 4 + 0) * 16 + c];
        w.y = W[(k4 * 4 + 1) * 16 + c];
        w.z = W[(k4 * 4 + 2) * 16 + c];
        w.w = W[(k4 * 4 + 3) * 16 + c];
        sWt4[i] = w;
    }
    if (t < 128) {
        int k4 = t >> 5, cc = t & 31;
        float4 wl, wr;
        wl.x = Wl[(k4 * 4 + 0) * 32 + cc]; wr.x = Wr[(k4 * 4 + 0) * 32 + cc];
        wl.y = Wl[(k4 * 4 + 1) * 32 + cc]; wr.y = Wr[(k4 * 4 + 1) * 32 + cc];
        wl.z = Wl[(k4 * 4 + 2) * 32 + cc]; wr.z = Wr[(k4 * 4 + 2) * 32 + cc];
        wl.w = Wl[(k4 * 4 + 3) * 32 + cc]; wr.w = Wr[(k4 * 4 + 3) * 32 + cc];
        sWlT[t] = wl; sWrT[t] = wr;
    }
    if (t >= 128 && t < 160) { sbl[t - 128] = bl[t - 128]; sbr[t - 128] = br[t - 128]; }
    __syncthreads();

    int n = t >> 4, c = t & 15;     // node pair (n, n+16), channel c
    float acc1 = b[c], acc2 = acc1;
#pragma unroll
    for (int k4 = 0; k4 < 32; k4++) {
        float4 wv = sWt4[k4 * 16 + c];
        float4 x1 = sx4[n * 32 + k4];
        float4 x2 = sx4[(n + 16) * 32 + k4];
        acc1 += x1.x * wv.x + x1.y * wv.y + x1.z * wv.z + x1.w * wv.w;
        acc2 += x2.x * wv.x + x2.y * wv.y + x2.z * wv.z + x2.w * wv.w;
    }
    unsigned gmask = 0xFFFFu << ((t & 31) & 16);
    float s1 = acc1, s2 = acc2;
#pragma unroll
    for (int o = 1; o < 16; o <<= 1) {
        s1 += __shfl_xor_sync(gmask, s1, o);
        s2 += __shfl_xor_sync(gmask, s2, o);
    }
    float d1 = acc1 - s1 * (1.f / 16.f);
    float d2 = acc2 - s2 * (1.f / 16.f);
    float q1 = d1 * d1, q2 = d2 * d2;
#pragma unroll
    for (int o = 1; o < 16; o <<= 1) {
        q1 += __shfl_xor_sync(gmask, q1, o);
        q2 += __shfl_xor_sync(gmask, q2, o);
    }
    float lw = lnw[c], lb = lnb[c];
    float v1 = fmaxf(d1 * rsqrtf(q1 * (1.f / 16.f) + EPSV) * lw + lb, 0.f);
    float v2 = fmaxf(d2 * rsqrtf(q2 * (1.f / 16.f) + EPSV) * lw + lb, 0.f);
    int g1 = n0 + n, g2 = n0 + n + 16;
    if (g1 < N) { d_h[g1 * 16 + c] = v1; out[g1 * 16 + c] = v1; }
    if (g2 < N) { d_h[g2 * 16 + c] = v2; out[g2 * 16 + c] = v2; }
    ((float*)sy4)[n * 16 + c] = v1;
    ((float*)sy4)[(n + 16) * 16 + c] = v2;
    __syncthreads();

#pragma unroll
    for (int p = 0; p < 2; p++) {
        int cc = c + p * 16;
        float al1 = sbl[cc], ar1 = sbr[cc], al2 = al1, ar2 = ar1;
#pragma unroll
        for (int k4 = 0; k4 < 4; k4++) {
            float4 wl = sWlT[k4 * 32 + cc];
            float4 wr = sWrT[k4 * 32 + cc];
            float4 x1 = sy4[n * 4 + k4];
            float4 x2 = sy4[(n + 16) * 4 + k4];
            al1 += x1.x * wl.x + x1.y * wl.y + x1.z * wl.z + x1.w * wl.w;
            ar1 += x1.x * wr.x + x1.y * wr.y + x1.z * wr.z + x1.w * wr.w;
            al2 += x2.x * wl.x + x2.y * wl.y + x2.z * wl.z + x2.w * wl.w;
            ar2 += x2.x * wr.x + x2.y * wr.y + x2.z * wr.z + x2.w * wr.w;
        }
        if (g1 < N) { d_xl[g1 * 32 + cc] = al1; d_xr[g1 * 32 + cc] = ar1; }
        if (g2 < N) { d_xl[g2 * 32 + cc] = al2; d_xr[g2 * 32 + cc] = ar2; }
    }
}

// ------- K_edge_csr: per-dst aggregation; 4 lanes/node; f32x2; depth-2 pipeline --
__global__ void __launch_bounds__(256) k_edge_csr(
    const float4* __restrict__ eattr,
    const float* __restrict__ We, const float* __restrict__ att,
    const float* __restrict__ gatb, int N, int zero23)
{
    __shared__ float sWe[128];
    __shared__ float sAtt[32];
    __shared__ float sGb[32];
    int t = threadIdx.x;
    if (zero23 && blockIdx.x == 0 && t == 255) { d_stats[2] = 0.0; d_stats[3] = 0.0; }
    if (t < 128) sWe[t] = We[t];
    else if (t < 160) sAtt[t - 128] = att[t - 128];
    else if (t < 192) sGb[t - 160] = gatb[t - 160];
    __syncthreads();

    int lane = t & 3;
    int slot = (blockIdx.x * 256 + t) >> 2;
    unsigned pmask = 0x3u << ((t & 31) & ~1);

    float s_loc = 0.f, q_loc = 0.f;
    if (slot < N) {
        int n = __ldg(&d_nperm[slot]);
        int cb = lane * 8;
        u64 w0[4], w1[4], w2[4], w3[4], at4[4], xr[4], acc[4];
#pragma unroll
        for (int i = 0; i < 4; i++) {
            w0[i]  = pack2(sWe[cb + 2 * i],      sWe[cb + 2 * i + 1]);
            w1[i]  = pack2(sWe[32 + cb + 2 * i], sWe[32 + cb + 2 * i + 1]);
            w2[i]  = pack2(sWe[64 + cb + 2 * i], sWe[64 + cb + 2 * i + 1]);
            w3[i]  = pack2(sWe[96 + cb + 2 * i], sWe[96 + cb + 2 * i + 1]);
            at4[i] = pack2(sAtt[cb + 2 * i],     sAtt[cb + 2 * i + 1]);
        }
        const ulonglong2* xlu = (const ulonglong2*)d_xl;
        const ulonglong2* xru = (const ulonglong2*)d_xr;
        {
            ulonglong2 X0 = xru[n * 8 + lane * 2];
            ulonglong2 X1 = xru[n * 8 + lane * 2 + 1];
            xr[0] = X0.x; xr[1] = X0.y; xr[2] = X1.x; xr[3] = X1.y;
        }
        float den;
        {   // self-loop (ew = 0)
            ulonglong2 A0 = xlu[n * 8 + lane * 2];
            ulonglong2 A1 = xlu[n * 8 + lane * 2 + 1];
            u64 a0 = A0.x, a1 = A0.y, a2 = A1.x, a3 = A1.y;
            u64 l0 = leaky2(add2(a0, xr[0]));
            u64 l1 = leaky2(add2(a1, xr[1]));
            u64 l2 = leaky2(add2(a2, xr[2]));
            u64 l3 = leaky2(add2(a3, xr[3]));
            u64 dd0 = fma2(l1, at4[1], mul2(l0, at4[0]));
            u64 dd1 = fma2(l3, at4[3], mul2(l2, at4[2]));
            float2 dv = unpack2(add2(dd0, dd1));
            float p = dv.x + dv.y;
            p += __shfl_xor_sync(pmask, p, 1);
            float ex = __expf(p);
            den = ex;
            u64 e2 = pack2(ex, ex);
            acc[0] = mul2(e2, a0); acc[1] = mul2(e2, a1);
            acc[2] = mul2(e2, a2); acc[3] = mul2(e2, a3);
        }
        int start = __ldg(&d_off[n]), deg = __ldg(&d_cnt[n]);
        const long long* qp = d_sep + start;
        long long qA = __ldg(&qp[0]);
        long long qB = __ldg(&qp[1]);
        long long qC = __ldg(&qp[2]);
        int s0 = (int)qA, i0 = (int)(qA >> 32);
        int s1 = (int)qB, i1 = (int)(qB >> 32);
        ulonglong2 A0a = __ldg(&xlu[s0 * 8 + lane * 2]);
        ulonglong2 A1a = __ldg(&xlu[s0 * 8 + lane * 2 + 1]);
        float4     EAa = __ldg(&eattr[i0]);
        ulonglong2 A0b = __ldg(&xlu[s1 * 8 + lane * 2]);
        ulonglong2 A1b = __ldg(&xlu[s1 * 8 + lane * 2 + 1]);
        float4     EAb = __ldg(&eattr[i1]);
        for (int j = 0; j < deg; j++) {
            u64 a0 = A0a.x, a1 = A0a.y, a2 = A1a.x, a3 = A1a.y;
            float4 ea = EAa;
            A0a = A0b; A1a = A1b; EAa = EAb;
            int sC = (int)qC, iC = (int)(qC >> 32);
            A0b = __ldg(&xlu[sC * 8 + lane * 2]);
            A1b = __ldg(&xlu[sC * 8 + lane * 2 + 1]);
            EAb = __ldg(&eattr[iC]);
            qC = __ldg(&qp[j + 3]);
            u64 eax = pack2(ea.x, ea.x), eay = pack2(ea.y, ea.y);
            u64 eaz = pack2(ea.z, ea.z), eaw = pack2(ea.w, ea.w);
            u64 m0 = fma2(eax, w0[0], fma2(eay, w1[0], fma2(eaz, w2[0], fma2(eaw, w3[0], add2(a0, xr[0])))));
            u64 m1 = fma2(eax, w0[1], fma2(eay, w1[1], fma2(eaz, w2[1], fma2(eaw, w3[1], add2(a1, xr[1])))));
            u64 m2 = fma2(eax, w0[2], fma2(eay, w1[2], fma2(eaz, w2[2], fma2(eaw, w3[2], add2(a2, xr[2])))));
            u64 m3 = fma2(eax, w0[3], fma2(eay, w1[3], fma2(eaz, w2[3], fma2(eaw, w3[3], add2(a3, xr[3])))));
            u64 dd0 = fma2(leaky2(m1), at4[1], mul2(leaky2(m0), at4[0]));
            u64 dd1 = fma2(leaky2(m3), at4[3], mul2(leaky2(m2), at4[2]));
            float2 dv = unpack2(add2(dd0, dd1));
            float pe = dv.x + dv.y;
            pe += __shfl_xor_sync(pmask, pe, 1);
            float exe = __expf(pe);
            den += exe;
            u64 e2 = pack2(exe, exe);
            acc[0] = fma2(e2, a0, acc[0]); acc[1] = fma2(e2, a1, acc[1]);
            acc[2] = fma2(e2, a2, acc[2]); acc[3] = fma2(e2, a3, acc[3]);
        }
        float inv = 1.f / den;
        u64 inv2 = pack2(inv, inv);
        u64 r0 = fma2(acc[0], inv2, pack2(sGb[cb],     sGb[cb + 1]));
        u64 r1 = fma2(acc[1], inv2, pack2(sGb[cb + 2], sGb[cb + 3]));
        u64 r2 = fma2(acc[2], inv2, pack2(sGb[cb + 4], sGb[cb + 5]));
        u64 r3 = fma2(acc[3], inv2, pack2(sGb[cb + 6], sGb[cb + 7]));
        ulonglong2 R0; R0.x = r0; R0.y = r1;
        ulonglong2 R1; R1.x = r2; R1.y = r3;
        ((ulonglong2*)d_g)[n * 8 + lane * 2]     = R0;
        ((ulonglong2*)d_g)[n * 8 + lane * 2 + 1] = R1;
        float2 v0 = unpack2(r0), v1 = unpack2(r1), v2 = unpack2(r2), v3 = unpack2(r3);
        s_loc = (v0.x + v0.y) + (v1.x + v1.y) + (v2.x + v2.y) + (v3.x + v3.y);
        q_loc = v0.x * v0.x + v0.y * v0.y + v1.x * v1.x + v1.y * v1.y
              + v2.x * v2.x + v2.y * v2.y + v3.x * v3.x + v3.y * v3.y;
    }
    blockReduceAdd2_256(s_loc, q_loc, &d_stats[0], &d_stats[1]);
}

// ------- K_tail: lin (graph_LN1+relu, @linW) -> stats -> gridbar ->
//         graph_LN2 + resid + relu -> h/out (+ next-layer transform for l=0).
__global__ void __launch_bounds__(256, 3) k_tail(
    const float* __restrict__ n1w, const float* __restrict__ n1b,
    const float* __restrict__ linW, const float* __restrict__ linb,
    const float* __restrict__ n2w, const float* __restrict__ n2b,
    const float* __restrict__ Wl, const float* __restrict__ bl,
    const float* __restrict__ Wr, const float* __restrict__ br,
    float* __restrict__ out, int N, int NBT, int layer)
{
    __shared__ alignas(16) float sLW[512];
    __shared__ alignas(16) float sWl[512], sWr[512];
    __shared__ float sn1w[32], sn1b[32], sbl[32], sbr[32];
    __shared__ float sn2w[16], sn2b[16], slb[16];
    int t = threadIdx.x, b = blockIdx.x;
    for (int i = t; i < 512; i += 256) {
        sLW[i] = linW[i];
        if (layer == 0) { sWl[i] = Wl[i]; sWr[i] = Wr[i]; }
    }
    if (t < 32)            { sn1w[t] = n1w[t];       sn1b[t] = n1b[t]; }
    else if (t < 64 && layer == 0) { sbl[t - 32] = bl[t - 32]; sbr[t - 32] = br[t - 32]; }
    if (t >= 64 && t < 80)  { sn2w[t - 64] = n2w[t - 64]; sn2b[t - 64] = n2b[t - 64]; }
    else if (t >= 80 && t < 96) { slb[t - 80] = linb[t - 80]; }
    __syncthreads();

    int n = b * 256 + t;
    u64 u[8];
    float s_loc = 0.f, q_loc = 0.f;
    if (n < N) {
        double mu1d  = d_stats[0] / (32.0 * N);
        double var1d = d_stats[1] / (32.0 * N) - mu1d * mu1d;
        float mu1  = (float)mu1d;
        float inv1 = rsqrtf((float)var1d + EPSV);
#pragma unroll
        for (int i = 0; i < 8; i++) u[i] = pack2(slb[2 * i], slb[2 * i + 1]);
        const float4* g4 = (const float4*)(d_g + n * 32);
#pragma unroll
        for (int kc = 0; kc < 4; kc++) {
            float4 ga = __ldg(&g4[kc * 2]);
            float4 gb = __ldg(&g4[kc * 2 + 1]);
            float tt[8];
            tt[0] = fmaxf((ga.x - mu1) * inv1 * sn1w[kc * 8 + 0] + sn1b[kc * 8 + 0], 0.f);
            tt[1] = fmaxf((ga.y - mu1) * inv1 * sn1w[kc * 8 + 1] + sn1b[kc * 8 + 1], 0.f);
            tt[2] = fmaxf((ga.z - mu1) * inv1 * sn1w[kc * 8 + 2] + sn1b[kc * 8 + 2], 0.f);
            tt[3] = fmaxf((ga.w - mu1) * inv1 * sn1w[kc * 8 + 3] + sn1b[kc * 8 + 3], 0.f);
            tt[4] = fmaxf((gb.x - mu1) * inv1 * sn1w[kc * 8 + 4] + sn1b[kc * 8 + 4], 0.f);
            tt[5] = fmaxf((gb.y - mu1) * inv1 * sn1w[kc * 8 + 5] + sn1b[kc * 8 + 5], 0.f);
            tt[6] = fmaxf((gb.z - mu1) * inv1 * sn1w[kc * 8 + 6] + sn1b[kc * 8 + 6], 0.f);
            tt[7] = fmaxf((gb.w - mu1) * inv1 * sn1w[kc * 8 + 7] + sn1b[kc * 8 + 7], 0.f);
#pragma unroll
            for (int kk = 0; kk < 8; kk++) {
                int k = kc * 8 + kk;
                u64 tk2 = pack2(tt[kk], tt[kk]);
                const u64* wrow = (const u64*)&sLW[k * 16];
#pragma unroll
                for (int i = 0; i < 8; i++) u[i] = fma2(tk2, wrow[i], u[i]);
            }
        }
#pragma unroll
        for (int i = 0; i < 8; i++) {
            float2 p = unpack2(u[i]);
            s_loc += p.x + p.y;
            q_loc += p.x * p.x + p.y * p.y;
        }
    }
    blockReduceAdd2_256(s_loc, q_loc, &d_stats[2], &d_stats[3]);
    gridbar(2 + layer, NBT);

    if (layer == 0 && b == 0 && t == 255) { d_stats[0] = 0.0; d_stats[1] = 0.0; }
    if (layer == 1) {   // restore zeroed counters for the next replay
        for (int i = b * 256 + t; i < N; i += NBT * 256) d_cnt[i] = 0;
        if (b < 4) d_dcnt[b * 256 + t] = 0;
    }
    if (n < N) {
        double mu2d  = d_stats[2] / (16.0 * N);
        double var2d = d_stats[3] / (16.0 * N) - mu2d * mu2d;
        float mu2  = (float)mu2d;
        float inv2 = rsqrtf((float)var2d + EPSV);
        float hn[16];
        const float4* h4 = (const float4*)(d_h + n * 16);
#pragma unroll
        for (int i = 0; i < 4; i++) {
            float4 hv = h4[i];
            float2 pa = unpack2(u[i * 2]), pb = unpack2(u[i * 2 + 1]);
            hn[i * 4 + 0] = fmaxf((pa.x - mu2) * inv2 * sn2w[i * 4 + 0] + sn2b[i * 4 + 0] + hv.x, 0.f);
            hn[i * 4 + 1] = fmaxf((pa.y - mu2) * inv2 * sn2w[i * 4 + 1] + sn2b[i * 4 + 1] + hv.y, 0.f);
            hn[i * 4 + 2] = fmaxf((pb.x - mu2) * inv2 * sn2w[i * 4 + 2] + sn2b[i * 4 + 2] + hv.z, 0.f);
            hn[i * 4 + 3] = fmaxf((pb.y - mu2) * inv2 * sn2w[i * 4 + 3] + sn2b[i * 4 + 3] + hv.w, 0.f);
        }
        float4* o4 = (float4*)(out + n * 16);
#pragma unroll
        for (int i = 0; i < 4; i++) {
            float4 ov = o4[i];
            ov.x = fmaxf(ov.x, hn[i * 4 + 0]);
            ov.y = fmaxf(ov.y, hn[i * 4 + 1]);
            ov.z = fmaxf(ov.z, hn[i * 4 + 2]);
            ov.w = fmaxf(ov.w, hn[i * 4 + 3]);
            o4[i] = ov;
        }
        if (layer == 0) {
            float4* hw = (float4*)(d_h + n * 16);
#pragma unroll
            for (int i = 0; i < 4; i++)
                hw[i] = make_float4(hn[i * 4], hn[i * 4 + 1], hn[i * 4 + 2], hn[i * 4 + 3]);
#pragma unroll
            for (int half = 0; half < 2; half++) {
                u64 xa[8], ra[8];
#pragma unroll
                for (int i = 0; i < 8; i++) {
                    xa[i] = pack2(sbl[half * 16 + 2 * i], sbl[half * 16 + 2 * i + 1]);
                    ra[i] = pack2(sbr[half * 16 + 2 * i], sbr[half * 16 + 2 * i + 1]);
                }
#pragma unroll
                for (int k = 0; k < 16; k++) {
                    u64 hk2 = pack2(hn[k], hn[k]);
                    const u64* wl = (const u64*)&sWl[k * 32 + half * 16];
                    const u64* wr = (const u64*)&sWr[k * 32 + half * 16];
#pragma unroll
                    for (int i = 0; i < 8; i++) {
                        xa[i] = fma2(hk2, wl[i], xa[i]);
                        ra[i] = fma2(hk2, wr[i], ra[i]);
                    }
                }
                ulonglong2* xo = (ulonglong2*)(d_xl + n * 32 + half * 16);
                ulonglong2* ro = (ulonglong2*)(d_xr + n * 32 + half * 16);
#pragma unroll
                for (int i = 0; i < 4; i++) {
                    ulonglong2 X; X.x = xa[2 * i]; X.y = xa[2 * i + 1]; xo[i] = X;
                    ulonglong2 R; R.x = ra[2 * i]; R.y = ra[2 * i + 1]; ro[i] = R;
                }
            }
        }
    }
}

// ---------------- launch ----------------
extern "C" void kernel_launch(void* const* d_in, const int* in_sizes, int n_in,
                              void* d_out, int out_size)
{
    const float* x     = (const float*)d_in[0];
    const int*   ei32  = (const int*)d_in[1];
    const float* eattr = (const float*)d_in[2];
    const float* embW  = (const float*)d_in[3];
    const float* embB  = (const float*)d_in[4];
    const float* ln0w  = (const float*)d_in[5];
    const float* ln0b  = (const float*)d_in[6];
    const float* Wl    = (const float*)d_in[7];
    const float* bl    = (const float*)d_in[8];
    const float* Wr    = (const float*)d_in[9];
    const float* br    = (const float*)d_in[10];
    const float* We    = (const float*)d_in[11];
    const float* att   = (const float*)d_in[12];
    const float* gatb  = (const float*)d_in[13];
    const float* n1w   = (const float*)d_in[14];
    const float* n1b   = (const float*)d_in[15];
    const float* linW  = (const float*)d_in[16];
    const float* linb  = (const float*)d_in[17];
    const float* n2w   = (const float*)d_in[18];
    const float* n2b   = (const float*)d_in[19];
    float* out = (float*)d_out;

    int N   = in_sizes[0] / 128;
    int E   = in_sizes[2] / 4;           // edge_attr is (E, 4)
    int NB  = (N + PB - 1) / PB;         // 196 (co-resident)
    int NBT = (N + 255) / 256;           // 391 <= 444 co-resident
    int nbe = (N + 31) / 32;

    k_hist   <<<(E + 255) / 256, 256>>>(ei32, E, N);                       // 1
    k_scan   <<<NB, PB>>>(N, NB);                                          // 2
    k_scatter<<<(E + 255) / 256, 256>>>(E);                                // 3
    k_embed  <<<nbe, 256>>>(x, embW, embB, ln0w, ln0b,
                            Wl, bl, Wr, br, out, N);                       // 4 (ncu)

    for (int l = 0; l < 2; l++) {
        k_edge_csr<<<(N * 4 + 255) / 256, 256>>>((const float4*)eattr,
                                                 We + l * 128, att + l * 32,
                                                 gatb + l * 32, N, l == 1); // 5, 7
        k_tail<<<NBT, 256>>>(n1w + l * 32, n1b + l * 32,
                             linW + l * 512, linb + l * 16,
                             n2w + l * 16, n2b + l * 16,
                             Wl + 512, bl + 32, Wr + 512, br + 32,
                             out, N, NBT, l);                               // 6, 8
    }
}

// round 16
// speedup vs baseline: 1.1559x; 1.0228x over previous
#include <cuda_runtime.h>

#define EPSV 1e-5f
#define NMAX 100000
#define EMAX 1600000
#define PB   512

typedef unsigned long long u64;

// ---------------- scratch (device globals; no allocation allowed) -------------
__device__ alignas(16) float  d_h  [NMAX * 16];
__device__ alignas(16) float  d_xl [NMAX * 32];
__device__ alignas(16) float  d_xr [NMAX * 32];
__device__ alignas(16) float  d_g  [NMAX * 32];
__device__ int       d_src [EMAX];
__device__ int       d_dst [EMAX];
__device__ alignas(16) long long d_sep[EMAX + 32]; // (eid<<32)|src permuted; padded .bss
__device__ int       d_cnt [NMAX];
__device__ int       d_off [NMAX];
__device__ int       d_cur [NMAX];
__device__ int       d_nperm[NMAX];
__device__ int       d_dcnt[1024];
__device__ int       d_dcur[1024];
__device__ int       d_bsum[256];
__device__ unsigned long long d_barc[4];
__device__ double    d_stats[4];  // [0],[1]: sum/sumsq of g; [2],[3]: of u

// ---------------- f32x2 packed helpers (sm_103a) ----------------
__device__ __forceinline__ u64 pack2(float x, float y) {
    u64 r; asm("mov.b64 %0, {%1, %2};" : "=l"(r) : "f"(x), "f"(y)); return r;
}
__device__ __forceinline__ float2 unpack2(u64 p) {
    float2 v; asm("mov.b64 {%0, %1}, %2;" : "=f"(v.x), "=f"(v.y) : "l"(p)); return v;
}
__device__ __forceinline__ u64 fma2(u64 a, u64 b, u64 c) {
    u64 r; asm("fma.rn.f32x2 %0, %1, %2, %3;" : "=l"(r) : "l"(a), "l"(b), "l"(c)); return r;
}
__device__ __forceinline__ u64 add2(u64 a, u64 b) {
    u64 r; asm("add.rn.f32x2 %0, %1, %2;" : "=l"(r) : "l"(a), "l"(b)); return r;
}
__device__ __forceinline__ u64 mul2(u64 a, u64 b) {
    u64 r; asm("mul.rn.f32x2 %0, %1, %2;" : "=l"(r) : "l"(a), "l"(b)); return r;
}
#define ABS2(a) ((a) & 0x7FFFFFFF7FFFFFFFULL)
#define K06 0x3F19999A3F19999AULL
#define K04 0x3ECCCCCD3ECCCCCDULL
__device__ __forceinline__ u64 leaky2(u64 m) { return fma2(ABS2(m), K04, mul2(m, K06)); }

__device__ __forceinline__ void gridbar(int idx, int NB) {
    __syncthreads();
    if (threadIdx.x == 0) {
        __threadfence();
        unsigned long long tk = atomicAdd(&d_barc[idx], 1ULL);
        unsigned long long target = (tk / NB + 1ULL) * (unsigned long long)NB;
        while (atomicAdd(&d_barc[idx], 0ULL) < target) { __nanosleep(64); }
    }
    __syncthreads();
}

__device__ __forceinline__ void blockReduceAdd2_256(float s, float q, double* o0, double* o1) {
    __shared__ float rs[8], rq[8];
#pragma unroll
    for (int o = 16; o; o >>= 1) {
        s += __shfl_xor_sync(0xffffffffu, s, o);
        q += __shfl_xor_sync(0xffffffffu, q, o);
    }
    int w = threadIdx.x >> 5, l = threadIdx.x & 31;
    if (l == 0) { rs[w] = s; rq[w] = q; }
    __syncthreads();
    if (w == 0) {
        s = (l < 8) ? rs[l] : 0.f;
        q = (l < 8) ? rq[l] : 0.f;
#pragma unroll
        for (int o = 4; o; o >>= 1) {
            s += __shfl_xor_sync(0xffffffffu, s, o);
            q += __shfl_xor_sync(0xffffffffu, q, o);
        }
        if (l == 0) { atomicAdd(o0, (double)s); atomicAdd(o1, (double)q); }
    }
}

// ------- K_fused0: blocks [0,nbe): embed+LN+transform; blocks [nbe,..): hist ------
// Embed: 32 nodes/block, thread = (node pair, channel); f32x2-packed GEMM.
__global__ void __launch_bounds__(256) k_fused0(
    const float* __restrict__ x, const float* __restrict__ W,
    const float* __restrict__ b, const float* __restrict__ lnw,
    const float* __restrict__ lnb,
    const float* __restrict__ Wl, const float* __restrict__ bl,
    const float* __restrict__ Wr, const float* __restrict__ br,
    const int* __restrict__ ei32,
    float* __restrict__ out, int N, int E, int nbe)
{
    int t = threadIdx.x;
    if (blockIdx.x >= nbe) {
        // ---- hist path ----
        bool is64 = true;
#pragma unroll
        for (int k = 0; k < 8; k++)
            if (__ldg(&ei32[2 * k + 1]) != 0) is64 = false;
        int i = (blockIdx.x - nbe) * 256 + t;
        if (i < 4) d_stats[i] = 0.0;
        if (i >= E) return;
        int s, d;
        if (is64) {
            const long long* e64 = (const long long*)ei32;
            s = (int)__ldcs(&e64[i]);
            d = (int)__ldcs(&e64[E + i]);
        } else {
            s = __ldcs(&ei32[i]);
            d = __ldcs(&ei32[E + i]);
        }
        s = min(max(s, 0), N - 1);
        d = min(max(d, 0), N - 1);
        d_src[i] = s;
        d_dst[i] = d;
        atomicAdd(&d_cnt[d], 1);
        return;
    }
    // ---- embed path ----
    __shared__ float4 sx4[32 * 32];     // 16KB
    __shared__ float4 sWt4[32 * 16];    // 8KB: sWt4[k4*16+c] = W[k4*4+j][c]
    __shared__ float4 sWlT[4 * 32];
    __shared__ float4 sWrT[4 * 32];
    __shared__ float4 sy4[32 * 4];
    __shared__ float  sbl[32], sbr[32];
    int n0 = blockIdx.x * 32;

    for (int i = t; i < 1024; i += 256) {
        int row = i >> 5, k4 = i & 31;
        int gn = n0 + row;
        sx4[i] = (gn < N) ? __ldcs(&((const float4*)x)[gn * 32 + k4])
                          : make_float4(0.f, 0.f, 0.f, 0.f);
    }
    for (int i = t; i < 512; i += 256) {
        int k4 = i >> 4, c = i & 15;
        float4 w;
        w.x = W[(k4 * 4 + 0) * 16 + c];
        w.y = W[(k4 * 4 + 1) * 16 + c];
        w.z = W[(k4 * 4 + 2) * 16 + c];
        w.w = W[(k4 * 4 + 3) * 16 + c];
        sWt4[i] = w;
    }
    if (t < 128) {
        int k4 = t >> 5, cc = t & 31;
        float4 wl, wr;
        wl.x = Wl[(k4 * 4 + 0) * 32 + cc]; wr.x = Wr[(k4 * 4 + 0) * 32 + cc];
        wl.y = Wl[(k4 * 4 + 1) * 32 + cc]; wr.y = Wr[(k4 * 4 + 1) * 32 + cc];
        wl.z = Wl[(k4 * 4 + 2) * 32 + cc]; wr.z = Wr[(k4 * 4 + 2) * 32 + cc];
        wl.w = Wl[(k4 * 4 + 3) * 32 + cc]; wr.w = Wr[(k4 * 4 + 3) * 32 + cc];
        sWlT[t] = wl; sWrT[t] = wr;
    }
    if (t >= 128 && t < 160) { sbl[t - 128] = bl[t - 128]; sbr[t - 128] = br[t - 128]; }
    __syncthreads();

    int n = t >> 4, c = t & 15;     // node pair (n, n+16), channel c
    const ulonglong2* sxu = (const ulonglong2*)sx4;
    const ulonglong2* swu = (const ulonglong2*)sWt4;
    u64 p1 = 0, p2 = 0;             // packed (even-k, odd-k) partials
#pragma unroll
    for (int k4 = 0; k4 < 32; k4++) {
        ulonglong2 wv = swu[k4 * 16 + c];
        ulonglong2 x1 = sxu[n * 32 + k4];
        ulonglong2 x2 = sxu[(n + 16) * 32 + k4];
        p1 = fma2(x1.x, wv.x, p1); p1 = fma2(x1.y, wv.y, p1);
        p2 = fma2(x2.x, wv.x, p2); p2 = fma2(x2.y, wv.y, p2);
    }
    float2 f1 = unpack2(p1), f2 = unpack2(p2);
    float bc = b[c];
    float acc1 = f1.x + f1.y + bc;
    float acc2 = f2.x + f2.y + bc;

    unsigned gmask = 0xFFFFu << ((t & 31) & 16);
    float s1 = acc1, s2 = acc2;
#pragma unroll
    for (int o = 1; o < 16; o <<= 1) {
        s1 += __shfl_xor_sync(gmask, s1, o);
        s2 += __shfl_xor_sync(gmask, s2, o);
    }
    float d1 = acc1 - s1 * (1.f / 16.f);
    float d2 = acc2 - s2 * (1.f / 16.f);
    float q1 = d1 * d1, q2 = d2 * d2;
#pragma unroll
    for (int o = 1; o < 16; o <<= 1) {
        q1 += __shfl_xor_sync(gmask, q1, o);
        q2 += __shfl_xor_sync(gmask, q2, o);
    }
    float lw = lnw[c], lb = lnb[c];
    float v1 = fmaxf(d1 * rsqrtf(q1 * (1.f / 16.f) + EPSV) * lw + lb, 0.f);
    float v2 = fmaxf(d2 * rsqrtf(q2 * (1.f / 16.f) + EPSV) * lw + lb, 0.f);
    int g1 = n0 + n, g2 = n0 + n + 16;
    if (g1 < N) { d_h[g1 * 16 + c] = v1; out[g1 * 16 + c] = v1; }
    if (g2 < N) { d_h[g2 * 16 + c] = v2; out[g2 * 16 + c] = v2; }
    ((float*)sy4)[n * 16 + c] = v1;
    ((float*)sy4)[(n + 16) * 16 + c] = v2;
    __syncthreads();

#pragma unroll
    for (int p = 0; p < 2; p++) {
        int cc = c + p * 16;
        float al1 = sbl[cc], ar1 = sbr[cc], al2 = al1, ar2 = ar1;
#pragma unroll
        for (int k4 = 0; k4 < 4; k4++) {
            float4 wl = sWlT[k4 * 32 + cc];
            float4 wr = sWrT[k4 * 32 + cc];
            float4 x1 = sy4[n * 4 + k4];
            float4 x2 = sy4[(n + 16) * 4 + k4];
            al1 += x1.x * wl.x + x1.y * wl.y + x1.z * wl.z + x1.w * wl.w;
            ar1 += x1.x * wr.x + x1.y * wr.y + x1.z * wr.z + x1.w * wr.w;
            al2 += x2.x * wl.x + x2.y * wl.y + x2.z * wl.z + x2.w * wl.w;
            ar2 += x2.x * wr.x + x2.y * wr.y + x2.z * wr.z + x2.w * wr.w;
        }
        if (g1 < N) { d_xl[g1 * 32 + cc] = al1; d_xr[g1 * 32 + cc] = ar1; }
        if (g2 < N) { d_xl[g2 * 32 + cc] = al2; d_xr[g2 * 32 + cc] = ar2; }
    }
}

// ------- K_scan: edge-offset scan + degree-sort of nodes (196 blocks) -------
__global__ void __launch_bounds__(PB) k_scan(int N, int NB) {
    __shared__ int ssc[PB];
    __shared__ int sbs[256];
    __shared__ int sd[1024];
    int t = threadIdx.x, b = blockIdx.x;
    int i = b * PB + t;

    int v = (i < N) ? d_cnt[i] : 0;
    if (i < N) atomicAdd(&d_dcnt[min(v, 1023)], 1);
    ssc[t] = v;
    __syncthreads();
#pragma unroll
    for (int o = 1; o < PB; o <<= 1) {
        int u = (t >= o) ? ssc[t - o] : 0;
        __syncthreads();
        ssc[t] += u;
        __syncthreads();
    }
    int incl = ssc[t];
    if (t == PB - 1) d_bsum[b] = incl;
    gridbar(0, NB);

    if (t < 256) sbs[t] = (t < NB) ? __ldcg(&d_bsum[t]) : 0;
    __syncthreads();
#pragma unroll
    for (int o = 1; o < 256; o <<= 1) {
        int u = 0;
        if (t < 256 && t >= o) u = sbs[t - o];
        __syncthreads();
        if (t < 256) sbs[t] += u;
        __syncthreads();
    }
    int base = (b > 0) ? sbs[b - 1] : 0;
    if (i < N) {
        int off = base + incl - v;
        d_off[i] = off;
        d_cur[i] = off;
    }
    if (b == 0) {
        int v0 = __ldcg(&d_dcnt[t]), v1 = __ldcg(&d_dcnt[t + 512]);
        sd[t] = v0; sd[t + 512] = v1;
        __syncthreads();
#pragma unroll
        for (int o = 1; o < 1024; o <<= 1) {
            int a0 = (t >= o) ? sd[t - o] : 0;
            int a1 = (t + 512 >= o) ? sd[t + 512 - o] : 0;
            __syncthreads();
            sd[t] += a0; sd[t + 512] += a1;
            __syncthreads();
        }
        d_dcur[t] = sd[t] - v0;
        d_dcur[t + 512] = sd[t + 512] - v1;
    }
    gridbar(1, NB);

    // scatter nodes into DESCENDING-degree order (LPT)
    int stride = NB * PB;
    for (int n = b * PB + t; n < N; n += stride) {
        int dg = min(__ldcg(&d_cnt[n]), 1023);
        int pos = atomicAdd(&d_dcur[dg], 1);
        d_nperm[N - 1 - pos] = n;
    }
}

// ------- K_scatter: permute (src, edge-id) into dst-grouped order, 8B/edge ------
__global__ void __launch_bounds__(256) k_scatter(int E) {
    int i = blockIdx.x * 256 + threadIdx.x;
    if (i >= E) return;
    int d = d_dst[i];
    int pos = atomicAdd(&d_cur[d], 1);
    d_sep[pos] = ((long long)i << 32) | (unsigned)d_src[i];
}

// ------- K_edge_csr: per-dst aggregation; 4 lanes/node; f32x2; depth-2 pipeline --
__global__ void __launch_bounds__(256) k_edge_csr(
    const float4* __restrict__ eattr,
    const float* __restrict__ We, const float* __restrict__ att,
    const float* __restrict__ gatb, int N, int zero23)
{
    __shared__ float sWe[128];
    __shared__ float sAtt[32];
    __shared__ float sGb[32];
    int t = threadIdx.x;
    if (zero23 && blockIdx.x == 0 && t == 255) { d_stats[2] = 0.0; d_stats[3] = 0.0; }
    if (t < 128) sWe[t] = We[t];
    else if (t < 160) sAtt[t - 128] = att[t - 128];
    else if (t < 192) sGb[t - 160] = gatb[t - 160];
    __syncthreads();

    int lane = t & 3;
    int slot = (blockIdx.x * 256 + t) >> 2;
    unsigned pmask = 0x3u << ((t & 31) & ~1);

    float s_loc = 0.f, q_loc = 0.f;
    if (slot < N) {
        int n = __ldg(&d_nperm[slot]);
        int cb = lane * 8;
        u64 w0[4], w1[4], w2[4], w3[4], at4[4], xr[4], acc[4];
#pragma unroll
        for (int i = 0; i < 4; i++) {
            w0[i]  = pack2(sWe[cb + 2 * i],      sWe[cb + 2 * i + 1]);
            w1[i]  = pack2(sWe[32 + cb + 2 * i], sWe[32 + cb + 2 * i + 1]);
            w2[i]  = pack2(sWe[64 + cb + 2 * i], sWe[64 + cb + 2 * i + 1]);
            w3[i]  = pack2(sWe[96 + cb + 2 * i], sWe[96 + cb + 2 * i + 1]);
            at4[i] = pack2(sAtt[cb + 2 * i],     sAtt[cb + 2 * i + 1]);
        }
        const ulonglong2* xlu = (const ulonglong2*)d_xl;
        const ulonglong2* xru = (const ulonglong2*)d_xr;
        {
            ulonglong2 X0 = xru[n * 8 + lane * 2];
            ulonglong2 X1 = xru[n * 8 + lane * 2 + 1];
            xr[0] = X0.x; xr[1] = X0.y; xr[2] = X1.x; xr[3] = X1.y;
        }
        float den;
        {   // self-loop (ew = 0)
            ulonglong2 A0 = xlu[n * 8 + lane * 2];
            ulonglong2 A1 = xlu[n * 8 + lane * 2 + 1];
            u64 a0 = A0.x, a1 = A0.y, a2 = A1.x, a3 = A1.y;
            u64 l0 = leaky2(add2(a0, xr[0]));
            u64 l1 = leaky2(add2(a1, xr[1]));
            u64 l2 = leaky2(add2(a2, xr[2]));
            u64 l3 = leaky2(add2(a3, xr[3]));
            u64 dd0 = fma2(l1, at4[1], mul2(l0, at4[0]));
            u64 dd1 = fma2(l3, at4[3], mul2(l2, at4[2]));
            float2 dv = unpack2(add2(dd0, dd1));
            float p = dv.x + dv.y;
            p += __shfl_xor_sync(pmask, p, 1);
            float ex = __expf(p);
            den = ex;
            u64 e2 = pack2(ex, ex);
            acc[0] = mul2(e2, a0); acc[1] = mul2(e2, a1);
            acc[2] = mul2(e2, a2); acc[3] = mul2(e2, a3);
        }
        int start = __ldg(&d_off[n]), deg = __ldg(&d_cnt[n]);
        const long long* qp = d_sep + start;
        long long qA = __ldg(&qp[0]);
        long long qB = __ldg(&qp[1]);
        long long qC = __ldg(&qp[2]);
        int s0 = (int)qA, i0 = (int)(qA >> 32);
        int s1 = (int)qB, i1 = (int)(qB >> 32);
        ulonglong2 A0a = __ldg(&xlu[s0 * 8 + lane * 2]);
        ulonglong2 A1a = __ldg(&xlu[s0 * 8 + lane * 2 + 1]);
        float4     EAa = __ldg(&eattr[i0]);
        ulonglong2 A0b = __ldg(&xlu[s1 * 8 + lane * 2]);
        ulonglong2 A1b = __ldg(&xlu[s1 * 8 + lane * 2 + 1]);
        float4     EAb = __ldg(&eattr[i1]);
        for (int j = 0; j < deg; j++) {
            u64 a0 = A0a.x, a1 = A0a.y, a2 = A1a.x, a3 = A1a.y;
            float4 ea = EAa;
            A0a = A0b; A1a = A1b; EAa = EAb;
            int sC = (int)qC, iC = (int)(qC >> 32);
            A0b = __ldg(&xlu[sC * 8 + lane * 2]);
            A1b = __ldg(&xlu[sC * 8 + lane * 2 + 1]);
            EAb = __ldg(&eattr[iC]);
            qC = __ldg(&qp[j + 3]);
            u64 eax = pack2(ea.x, ea.x), eay = pack2(ea.y, ea.y);
            u64 eaz = pack2(ea.z, ea.z), eaw = pack2(ea.w, ea.w);
            u64 m0 = fma2(eax, w0[0], fma2(eay, w1[0], fma2(eaz, w2[0], fma2(eaw, w3[0], add2(a0, xr[0])))));
            u64 m1 = fma2(eax, w0[1], fma2(eay, w1[1], fma2(eaz, w2[1], fma2(eaw, w3[1], add2(a1, xr[1])))));
            u64 m2 = fma2(eax, w0[2], fma2(eay, w1[2], fma2(eaz, w2[2], fma2(eaw, w3[2], add2(a2, xr[2])))));
            u64 m3 = fma2(eax, w0[3], fma2(eay, w1[3], fma2(eaz, w2[3], fma2(eaw, w3[3], add2(a3, xr[3])))));
            u64 dd0 = fma2(leaky2(m1), at4[1], mul2(leaky2(m0), at4[0]));
            u64 dd1 = fma2(leaky2(m3), at4[3], mul2(leaky2(m2), at4[2]));
            float2 dv = unpack2(add2(dd0, dd1));
            float pe = dv.x + dv.y;
            pe += __shfl_xor_sync(pmask, pe, 1);
            float exe = __expf(pe);
            den += exe;
            u64 e2 = pack2(exe, exe);
            acc[0] = fma2(e2, a0, acc[0]); acc[1] = fma2(e2, a1, acc[1]);
            acc[2] = fma2(e2, a2, acc[2]); acc[3] = fma2(e2, a3, acc[3]);
        }
        float inv = 1.f / den;
        u64 inv2 = pack2(inv, inv);
        u64 r0 = fma2(acc[0], inv2, pack2(sGb[cb],     sGb[cb + 1]));
        u64 r1 = fma2(acc[1], inv2, pack2(sGb[cb + 2], sGb[cb + 3]));
        u64 r2 = fma2(acc[2], inv2, pack2(sGb[cb + 4], sGb[cb + 5]));
        u64 r3 = fma2(acc[3], inv2, pack2(sGb[cb + 6], sGb[cb + 7]));
        ulonglong2 R0; R0.x = r0; R0.y = r1;
        ulonglong2 R1; R1.x = r2; R1.y = r3;
        ((ulonglong2*)d_g)[n * 8 + lane * 2]     = R0;
        ((ulonglong2*)d_g)[n * 8 + lane * 2 + 1] = R1;
        float2 v0 = unpack2(r0), v1 = unpack2(r1), v2 = unpack2(r2), v3 = unpack2(r3);
        s_loc = (v0.x + v0.y) + (v1.x + v1.y) + (v2.x + v2.y) + (v3.x + v3.y);
        q_loc = v0.x * v0.x + v0.y * v0.y + v1.x * v1.x + v1.y * v1.y
              + v2.x * v2.x + v2.y * v2.y + v3.x * v3.x + v3.y * v3.y;
    }
    blockReduceAdd2_256(s_loc, q_loc, &d_stats[0], &d_stats[1]);
}

// ------- K_tail: lin (graph_LN1+relu, @linW) -> stats -> gridbar ->
//         graph_LN2 + resid + relu -> h/out (+ next-layer transform for l=0).
__global__ void __launch_bounds__(256, 3) k_tail(
    const float* __restrict__ n1w, const float* __restrict__ n1b,
    const float* __restrict__ linW, const float* __restrict__ linb,
    const float* __restrict__ n2w, const float* __restrict__ n2b,
    const float* __restrict__ Wl, const float* __restrict__ bl,
    const float* __restrict__ Wr, const float* __restrict__ br,
    float* __restrict__ out, int N, int NBT, int layer)
{
    __shared__ alignas(16) float sLW[512];
    __shared__ alignas(16) float sWl[512], sWr[512];
    __shared__ float sn1w[32], sn1b[32], sbl[32], sbr[32];
    __shared__ float sn2w[16], sn2b[16], slb[16];
    int t = threadIdx.x, b = blockIdx.x;
    for (int i = t; i < 512; i += 256) {
        sLW[i] = linW[i];
        if (layer == 0) { sWl[i] = Wl[i]; sWr[i] = Wr[i]; }
    }
    if (t < 32)            { sn1w[t] = n1w[t];       sn1b[t] = n1b[t]; }
    else if (t < 64 && layer == 0) { sbl[t - 32] = bl[t - 32]; sbr[t - 32] = br[t - 32]; }
    if (t >= 64 && t < 80)  { sn2w[t - 64] = n2w[t - 64]; sn2b[t - 64] = n2b[t - 64]; }
    else if (t >= 80 && t < 96) { slb[t - 80] = linb[t - 80]; }
    __syncthreads();

    int n = b * 256 + t;
    u64 u[8];
    float s_loc = 0.f, q_loc = 0.f;
    if (n < N) {
        double mu1d  = d_stats[0] / (32.0 * N);
        double var1d = d_stats[1] / (32.0 * N) - mu1d * mu1d;
        float mu1  = (float)mu1d;
        float inv1 = rsqrtf((float)var1d + EPSV);
#pragma unroll
        for (int i = 0; i < 8; i++) u[i] = pack2(slb[2 * i], slb[2 * i + 1]);
        const float4* g4 = (const float4*)(d_g + n * 32);
#pragma unroll
        for (int kc = 0; kc < 4; kc++) {
            float4 ga = __ldg(&g4[kc * 2]);
            float4 gb = __ldg(&g4[kc * 2 + 1]);
            float tt[8];
            tt[0] = fmaxf((ga.x - mu1) * inv1 * sn1w[kc * 8 + 0] + sn1b[kc * 8 + 0], 0.f);
            tt[1] = fmaxf((ga.y - mu1) * inv1 * sn1w[kc * 8 + 1] + sn1b[kc * 8 + 1], 0.f);
            tt[2] = fmaxf((ga.z - mu1) * inv1 * sn1w[kc * 8 + 2] + sn1b[kc * 8 + 2], 0.f);
            tt[3] = fmaxf((ga.w - mu1) * inv1 * sn1w[kc * 8 + 3] + sn1b[kc * 8 + 3], 0.f);
            tt[4] = fmaxf((gb.x - mu1) * inv1 * sn1w[kc * 8 + 4] + sn1b[kc * 8 + 4], 0.f);
            tt[5] = fmaxf((gb.y - mu1) * inv1 * sn1w[kc * 8 + 5] + sn1b[kc * 8 + 5], 0.f);
            tt[6] = fmaxf((gb.z - mu1) * inv1 * sn1w[kc * 8 + 6] + sn1b[kc * 8 + 6], 0.f);
            tt[7] = fmaxf((gb.w - mu1) * inv1 * sn1w[kc * 8 + 7] + sn1b[kc * 8 + 7], 0.f);
#pragma unroll
            for (int kk = 0; kk < 8; kk++) {
                int k = kc * 8 + kk;
                u64 tk2 = pack2(tt[kk], tt[kk]);
                const u64* wrow = (const u64*)&sLW[k * 16];
#pragma unroll
                for (int i = 0; i < 8; i++) u[i] = fma2(tk2, wrow[i], u[i]);
            }
        }
#pragma unroll
        for (int i = 0; i < 8; i++) {
            float2 p = unpack2(u[i]);
            s_loc += p.x + p.y;
            q_loc += p.x * p.x + p.y * p.y;
        }
    }
    blockReduceAdd2_256(s_loc, q_loc, &d_stats[2], &d_stats[3]);
    gridbar(2 + layer, NBT);

    if (layer == 0 && b == 0 && t == 255) { d_stats[0] = 0.0; d_stats[1] = 0.0; }
    if (layer == 1) {   // restore zeroed counters for the next replay
        for (int i = b * 256 + t; i < N; i += NBT * 256) d_cnt[i] = 0;
        if (b < 4) d_dcnt[b * 256 + t] = 0;
    }
    if (n < N) {
        double mu2d  = d_stats[2] / (16.0 * N);
        double var2d = d_stats[3] / (16.0 * N) - mu2d * mu2d;
        float mu2  = (float)mu2d;
        float inv2 = rsqrtf((float)var2d + EPSV);
        float hn[16];
        const float4* h4 = (const float4*)(d_h + n * 16);
#pragma unroll
        for (int i = 0; i < 4; i++) {
            float4 hv = h4[i];
            float2 pa = unpack2(u[i * 2]), pb = unpack2(u[i * 2 + 1]);
            hn[i * 4 + 0] = fmaxf((pa.x - mu2) * inv2 * sn2w[i * 4 + 0] + sn2b[i * 4 + 0] + hv.x, 0.f);
            hn[i * 4 + 1] = fmaxf((pa.y - mu2) * inv2 * sn2w[i * 4 + 1] + sn2b[i * 4 + 1] + hv.y, 0.f);
            hn[i * 4 + 2] = fmaxf((pb.x - mu2) * inv2 * sn2w[i * 4 + 2] + sn2b[i * 4 + 2] + hv.z, 0.f);
            hn[i * 4 + 3] = fmaxf((pb.y - mu2) * inv2 * sn2w[i * 4 + 3] + sn2b[i * 4 + 3] + hv.w, 0.f);
        }
        float4* o4 = (float4*)(out + n * 16);
#pragma unroll
        for (int i = 0; i < 4; i++) {
            float4 ov = o4[i];
            ov.x = fmaxf(ov.x, hn[i * 4 + 0]);
            ov.y = fmaxf(ov.y, hn[i * 4 + 1]);
            ov.z = fmaxf(ov.z, hn[i * 4 + 2]);
            ov.w = fmaxf(ov.w, hn[i * 4 + 3]);
            o4[i] = ov;
        }
        if (layer == 0) {
            float4* hw = (float4*)(d_h + n * 16);
#pragma unroll
            for (int i = 0; i < 4; i++)
                hw[i] = make_float4(hn[i * 4], hn[i * 4 + 1], hn[i * 4 + 2], hn[i * 4 + 3]);
#pragma unroll
            for (int half = 0; half < 2; half++) {
                u64 xa[8], ra[8];
#pragma unroll
                for (int i = 0; i < 8; i++) {
                    xa[i] = pack2(sbl[half * 16 + 2 * i], sbl[half * 16 + 2 * i + 1]);
                    ra[i] = pack2(sbr[half * 16 + 2 * i], sbr[half * 16 + 2 * i + 1]);
                }
#pragma unroll
                for (int k = 0; k < 16; k++) {
                    u64 hk2 = pack2(hn[k], hn[k]);
                    const u64* wl = (const u64*)&sWl[k * 32 + half * 16];
                    const u64* wr = (const u64*)&sWr[k * 32 + half * 16];
#pragma unroll
                    for (int i = 0; i < 8; i++) {
                        xa[i] = fma2(hk2, wl[i], xa[i]);
                        ra[i] = fma2(hk2, wr[i], ra[i]);
                    }
                }
                ulonglong2* xo = (ulonglong2*)(d_xl + n * 32 + half * 16);
                ulonglong2* ro = (ulonglong2*)(d_xr + n * 32 + half * 16);
#pragma unroll
                for (int i = 0; i < 4; i++) {
                    ulonglong2 X; X.x = xa[2 * i]; X.y = xa[2 * i + 1]; xo[i] = X;
                    ulonglong2 R; R.x = ra[2 * i]; R.y = ra[2 * i + 1]; ro[i] = R;
                }
            }
        }
    }
}

// ---------------- launch ----------------
extern "C" void kernel_launch(void* const* d_in, const int* in_sizes, int n_in,
                              void* d_out, int out_size)
{
    const float* x     = (const float*)d_in[0];
    const int*   ei32  = (const int*)d_in[1];
    const float* eattr = (const float*)d_in[2];
    const float* embW  = (const float*)d_in[3];
    const float* embB  = (const float*)d_in[4];
    const float* ln0w  = (const float*)d_in[5];
    const float* ln0b  = (const float*)d_in[6];
    const float* Wl    = (const float*)d_in[7];
    const float* bl    = (const float*)d_in[8];
    const float* Wr    = (const float*)d_in[9];
    const float* br    = (const float*)d_in[10];
    const float* We    = (const float*)d_in[11];
    const float* att   = (const float*)d_in[12];
    const float* gatb  = (const float*)d_in[13];
    const float* n1w   = (const float*)d_in[14];
    const float* n1b   = (const float*)d_in[15];
    const float* linW  = (const float*)d_in[16];
    const float* linb  = (const float*)d_in[17];
    const float* n2w   = (const float*)d_in[18];
    const float* n2b   = (const float*)d_in[19];
    float* out = (float*)d_out;

    int N   = in_sizes[0] / 128;
    int E   = in_sizes[2] / 4;           // edge_attr is (E, 4)
    int NB  = (N + PB - 1) / PB;         // 196 (co-resident)
    int NBT = (N + 255) / 256;           // 391 <= 444 co-resident
    int nbe = (N + 31) / 32;
    int nbh = (E + 255) / 256;

    k_fused0 <<<nbe + nbh, 256>>>(x, embW, embB, ln0w, ln0b,
                                  Wl, bl, Wr, br, ei32, out, N, E, nbe);   // 1
    k_scan   <<<NB, PB>>>(N, NB);                                          // 2
    k_scatter<<<(E + 255) / 256, 256>>>(E);                                // 3

    for (int l = 0; l < 2; l++) {
        k_edge_csr<<<(N * 4 + 255) / 256, 256>>>((const float4*)eattr,
                                                 We + l * 128, att + l * 32,
                                                 gatb + l * 32, N, l == 1); // 4 (ncu), 6
        k_tail<<<NBT, 256>>>(n1w + l * 32, n1b + l * 32,
                             linW + l * 512, linb + l * 16,
                             n2w + l * 16, n2b + l * 16,
                             Wl + 512, bl + 32, Wr + 512, br + 32,
                             out, N, NBT, l);                               // 5, 7
    }
}

// round 17
// speedup vs baseline: 1.1680x; 1.0105x over previous
#include <cuda_runtime.h>

#define EPSV 1e-5f
#define NMAX 100000
#define EMAX 1600000
#define PB   512

typedef unsigned long long u64;

// ---------------- scratch (device globals; no allocation allowed) -------------
__device__ alignas(16) float  d_h  [NMAX * 16];
__device__ alignas(16) float  d_xl [NMAX * 32];
__device__ alignas(16) float  d_xr [NMAX * 32];
__device__ alignas(16) float  d_g  [NMAX * 32];
__device__ int       d_src [EMAX];
__device__ int       d_dst [EMAX];
__device__ alignas(16) long long d_sep[EMAX + 32]; // (eid<<32)|src permuted; padded .bss
__device__ int       d_cnt [NMAX];
__device__ int       d_off [NMAX];
__device__ int       d_cur [NMAX];
__device__ int       d_nperm[NMAX];
__device__ int       d_dcnt[1024];
__device__ int       d_dcur[1024];
__device__ int       d_bsum[256];
__device__ unsigned long long d_barc[4];
__device__ double    d_stats[4];  // [0],[1]: sum/sumsq of g; [2],[3]: of u

// ---------------- f32x2 packed helpers (sm_103a) ----------------
__device__ __forceinline__ u64 pack2(float x, float y) {
    u64 r; asm("mov.b64 %0, {%1, %2};" : "=l"(r) : "f"(x), "f"(y)); return r;
}
__device__ __forceinline__ float2 unpack2(u64 p) {
    float2 v; asm("mov.b64 {%0, %1}, %2;" : "=f"(v.x), "=f"(v.y) : "l"(p)); return v;
}
__device__ __forceinline__ u64 fma2(u64 a, u64 b, u64 c) {
    u64 r; asm("fma.rn.f32x2 %0, %1, %2, %3;" : "=l"(r) : "l"(a), "l"(b), "l"(c)); return r;
}
__device__ __forceinline__ u64 add2(u64 a, u64 b) {
    u64 r; asm("add.rn.f32x2 %0, %1, %2;" : "=l"(r) : "l"(a), "l"(b)); return r;
}
__device__ __forceinline__ u64 mul2(u64 a, u64 b) {
    u64 r; asm("mul.rn.f32x2 %0, %1, %2;" : "=l"(r) : "l"(a), "l"(b)); return r;
}
#define ABS2(a) ((a) & 0x7FFFFFFF7FFFFFFFULL)
#define K06 0x3F19999A3F19999AULL
#define K04 0x3ECCCCCD3ECCCCCDULL
__device__ __forceinline__ u64 leaky2(u64 m) { return fma2(ABS2(m), K04, mul2(m, K06)); }

__device__ __forceinline__ void gridbar(int idx, int NB) {
    __syncthreads();
    if (threadIdx.x == 0) {
        __threadfence();
        unsigned long long tk = atomicAdd(&d_barc[idx], 1ULL);
        unsigned long long target = (tk / NB + 1ULL) * (unsigned long long)NB;
        while (atomicAdd(&d_barc[idx], 0ULL) < target) { __nanosleep(64); }
    }
    __syncthreads();
}

__device__ __forceinline__ void blockReduceAdd2_256(float s, float q, double* o0, double* o1) {
    __shared__ float rs[8], rq[8];
#pragma unroll
    for (int o = 16; o; o >>= 1) {
        s += __shfl_xor_sync(0xffffffffu, s, o);
        q += __shfl_xor_sync(0xffffffffu, q, o);
    }
    int w = threadIdx.x >> 5, l = threadIdx.x & 31;
    if (l == 0) { rs[w] = s; rq[w] = q; }
    __syncthreads();
    if (w == 0) {
        s = (l < 8) ? rs[l] : 0.f;
        q = (l < 8) ? rq[l] : 0.f;
#pragma unroll
        for (int o = 4; o; o >>= 1) {
            s += __shfl_xor_sync(0xffffffffu, s, o);
            q += __shfl_xor_sync(0xffffffffu, q, o);
        }
        if (l == 0) { atomicAdd(o0, (double)s); atomicAdd(o1, (double)q); }
    }
}

// ------- K_hist: decode edge_index + clamp + store + dst histogram + zero stats --
__global__ void __launch_bounds__(256) k_hist(const int* __restrict__ ei32, int E, int N) {
    bool is64 = true;
#pragma unroll
    for (int k = 0; k < 8; k++)
        if (__ldg(&ei32[2 * k + 1]) != 0) is64 = false;
    int i = blockIdx.x * 256 + threadIdx.x;
    if (i < 4) d_stats[i] = 0.0;
    if (i >= E) return;
    int s, d;
    if (is64) {
        const long long* e64 = (const long long*)ei32;
        s = (int)__ldcs(&e64[i]);
        d = (int)__ldcs(&e64[E + i]);
    } else {
        s = __ldcs(&ei32[i]);
        d = __ldcs(&ei32[E + i]);
    }
    s = min(max(s, 0), N - 1);
    d = min(max(d, 0), N - 1);
    d_src[i] = s;
    d_dst[i] = d;
    atomicAdd(&d_cnt[d], 1);
}

// ------- K_embed: h = relu(node_LN(x@W+b)); out=h; xl/xr for layer 0 ------------
// 32 nodes/block; f32x2-packed GEMM. Runs on a forked stream, overlapped with
// the hist->scan->scatter chain (fully independent data).
__global__ void __launch_bounds__(256) k_embed(
    const float* __restrict__ x, const float* __restrict__ W,
    const float* __restrict__ b, const float* __restrict__ lnw,
    const float* __restrict__ lnb,
    const float* __restrict__ Wl, const float* __restrict__ bl,
    const float* __restrict__ Wr, const float* __restrict__ br,
    float* __restrict__ out, int N)
{
    __shared__ float4 sx4[32 * 32];     // 16KB
    __shared__ float4 sWt4[32 * 16];    // 8KB
    __shared__ float4 sWlT[4 * 32];
    __shared__ float4 sWrT[4 * 32];
    __shared__ float4 sy4[32 * 4];
    __shared__ float  sbl[32], sbr[32];
    int t = threadIdx.x;
    int n0 = blockIdx.x * 32;

    for (int i = t; i < 1024; i += 256) {
        int row = i >> 5, k4 = i & 31;
        int gn = n0 + row;
        sx4[i] = (gn < N) ? __ldcs(&((const float4*)x)[gn * 32 + k4])
                          : make_float4(0.f, 0.f, 0.f, 0.f);
    }
    for (int i = t; i < 512; i += 256) {
        int k4 = i >> 4, c = i & 15;
        float4 w;
        w.x = W[(k4 * 4 + 0) * 16 + c];
        w.y = W[(k4 * 4 + 1) * 16 + c];
        w.z = W[(k4 * 4 + 2) * 16 + c];
        w.w = W[(k4 * 4 + 3) * 16 + c];
        sWt4[i] = w;
    }
    if (t < 128) {
        int k4 = t >> 5, cc = t & 31;
        float4 wl, wr;
        wl.x = Wl[(k4 * 4 + 0) * 32 + cc]; wr.x = Wr[(k4 * 4 + 0) * 32 + cc];
        wl.y = Wl[(k4 * 4 + 1) * 32 + cc]; wr.y = Wr[(k4 * 4 + 1) * 32 + cc];
        wl.z = Wl[(k4 * 4 + 2) * 32 + cc]; wr.z = Wr[(k4 * 4 + 2) * 32 + cc];
        wl.w = Wl[(k4 * 4 + 3) * 32 + cc]; wr.w = Wr[(k4 * 4 + 3) * 32 + cc];
        sWlT[t] = wl; sWrT[t] = wr;
    }
    if (t >= 128 && t < 160) { sbl[t - 128] = bl[t - 128]; sbr[t - 128] = br[t - 128]; }
    __syncthreads();

    int n = t >> 4, c = t & 15;     // node pair (n, n+16), channel c
    const ulonglong2* sxu = (const ulonglong2*)sx4;
    const ulonglong2* swu = (const ulonglong2*)sWt4;
    u64 p1 = 0, p2 = 0;
#pragma unroll
    for (int k4 = 0; k4 < 32; k4++) {
        ulonglong2 wv = swu[k4 * 16 + c];
        ulonglong2 x1 = sxu[n * 32 + k4];
        ulonglong2 x2 = sxu[(n + 16) * 32 + k4];
        p1 = fma2(x1.x, wv.x, p1); p1 = fma2(x1.y, wv.y, p1);
        p2 = fma2(x2.x, wv.x, p2); p2 = fma2(x2.y, wv.y, p2);
    }
    float2 f1 = unpack2(p1), f2 = unpack2(p2);
    float bc = b[c];
    float acc1 = f1.x + f1.y + bc;
    float acc2 = f2.x + f2.y + bc;

    unsigned gmask = 0xFFFFu << ((t & 31) & 16);
    float s1 = acc1, s2 = acc2;
#pragma unroll
    for (int o = 1; o < 16; o <<= 1) {
        s1 += __shfl_xor_sync(gmask, s1, o);
        s2 += __shfl_xor_sync(gmask, s2, o);
    }
    float d1 = acc1 - s1 * (1.f / 16.f);
    float d2 = acc2 - s2 * (1.f / 16.f);
    float q1 = d1 * d1, q2 = d2 * d2;
#pragma unroll
    for (int o = 1; o < 16; o <<= 1) {
        q1 += __shfl_xor_sync(gmask, q1, o);
        q2 += __shfl_xor_sync(gmask, q2, o);
    }
    float lw = lnw[c], lb = lnb[c];
    float v1 = fmaxf(d1 * rsqrtf(q1 * (1.f / 16.f) + EPSV) * lw + lb, 0.f);
    float v2 = fmaxf(d2 * rsqrtf(q2 * (1.f / 16.f) + EPSV) * lw + lb, 0.f);
    int g1 = n0 + n, g2 = n0 + n + 16;
    if (g1 < N) { d_h[g1 * 16 + c] = v1; out[g1 * 16 + c] = v1; }
    if (g2 < N) { d_h[g2 * 16 + c] = v2; out[g2 * 16 + c] = v2; }
    ((float*)sy4)[n * 16 + c] = v1;
    ((float*)sy4)[(n + 16) * 16 + c] = v2;
    __syncthreads();

#pragma unroll
    for (int p = 0; p < 2; p++) {
        int cc = c + p * 16;
        float al1 = sbl[cc], ar1 = sbr[cc], al2 = al1, ar2 = ar1;
#pragma unroll
        for (int k4 = 0; k4 < 4; k4++) {
            float4 wl = sWlT[k4 * 32 + cc];
            float4 wr = sWrT[k4 * 32 + cc];
            float4 x1 = sy4[n * 4 + k4];
            float4 x2 = sy4[(n + 16) * 4 + k4];
            al1 += x1.x * wl.x + x1.y * wl.y + x1.z * wl.z + x1.w * wl.w;
            ar1 += x1.x * wr.x + x1.y * wr.y + x1.z * wr.z + x1.w * wr.w;
            al2 += x2.x * wl.x + x2.y * wl.y + x2.z * wl.z + x2.w * wl.w;
            ar2 += x2.x * wr.x + x2.y * wr.y + x2.z * wr.z + x2.w * wr.w;
        }
        if (g1 < N) { d_xl[g1 * 32 + cc] = al1; d_xr[g1 * 32 + cc] = ar1; }
        if (g2 < N) { d_xl[g2 * 32 + cc] = al2; d_xr[g2 * 32 + cc] = ar2; }
    }
}

// ------- K_scan: edge-offset scan + degree-sort of nodes (196 blocks) -------
__global__ void __launch_bounds__(PB) k_scan(int N, int NB) {
    __shared__ int ssc[PB];
    __shared__ int sbs[256];
    __shared__ int sd[1024];
    int t = threadIdx.x, b = blockIdx.x;
    int i = b * PB + t;

    int v = (i < N) ? d_cnt[i] : 0;
    if (i < N) atomicAdd(&d_dcnt[min(v, 1023)], 1);
    ssc[t] = v;
    __syncthreads();
#pragma unroll
    for (int o = 1; o < PB; o <<= 1) {
        int u = (t >= o) ? ssc[t - o] : 0;
        __syncthreads();
        ssc[t] += u;
        __syncthreads();
    }
    int incl = ssc[t];
    if (t == PB - 1) d_bsum[b] = incl;
    gridbar(0, NB);

    if (t < 256) sbs[t] = (t < NB) ? __ldcg(&d_bsum[t]) : 0;
    __syncthreads();
#pragma unroll
    for (int o = 1; o < 256; o <<= 1) {
        int u = 0;
        if (t < 256 && t >= o) u = sbs[t - o];
        __syncthreads();
        if (t < 256) sbs[t] += u;
        __syncthreads();
    }
    int base = (b > 0) ? sbs[b - 1] : 0;
    if (i < N) {
        int off = base + incl - v;
        d_off[i] = off;
        d_cur[i] = off;
    }
    if (b == 0) {
        int v0 = __ldcg(&d_dcnt[t]), v1 = __ldcg(&d_dcnt[t + 512]);
        sd[t] = v0; sd[t + 512] = v1;
        __syncthreads();
#pragma unroll
        for (int o = 1; o < 1024; o <<= 1) {
            int a0 = (t >= o) ? sd[t - o] : 0;
            int a1 = (t + 512 >= o) ? sd[t + 512 - o] : 0;
            __syncthreads();
            sd[t] += a0; sd[t + 512] += a1;
            __syncthreads();
        }
        d_dcur[t] = sd[t] - v0;
        d_dcur[t + 512] = sd[t + 512] - v1;
    }
    gridbar(1, NB);

    // scatter nodes into DESCENDING-degree order (LPT)
    int stride = NB * PB;
    for (int n = b * PB + t; n < N; n += stride) {
        int dg = min(__ldcg(&d_cnt[n]), 1023);
        int pos = atomicAdd(&d_dcur[dg], 1);
        d_nperm[N - 1 - pos] = n;
    }
}

// ------- K_scatter: permute (src, edge-id) into dst-grouped order, 8B/edge ------
__global__ void __launch_bounds__(256) k_scatter(int E) {
    int i = blockIdx.x * 256 + threadIdx.x;
    if (i >= E) return;
    int d = d_dst[i];
    int pos = atomicAdd(&d_cur[d], 1);
    d_sep[pos] = ((long long)i << 32) | (unsigned)d_src[i];
}

// ------- K_edge_csr: per-dst aggregation; 4 lanes/node; f32x2; depth-2 pipeline --
__global__ void __launch_bounds__(256) k_edge_csr(
    const float4* __restrict__ eattr,
    const float* __restrict__ We, const float* __restrict__ att,
    const float* __restrict__ gatb, int N, int zero23)
{
    __shared__ float sWe[128];
    __shared__ float sAtt[32];
    __shared__ float sGb[32];
    int t = threadIdx.x;
    if (zero23 && blockIdx.x == 0 && t == 255) { d_stats[2] = 0.0; d_stats[3] = 0.0; }
    if (t < 128) sWe[t] = We[t];
    else if (t < 160) sAtt[t - 128] = att[t - 128];
    else if (t < 192) sGb[t - 160] = gatb[t - 160];
    __syncthreads();

    int lane = t & 3;
    int slot = (blockIdx.x * 256 + t) >> 2;
    unsigned pmask = 0x3u << ((t & 31) & ~1);

    float s_loc = 0.f, q_loc = 0.f;
    if (slot < N) {
        int n = __ldg(&d_nperm[slot]);
        int cb = lane * 8;
        u64 w0[4], w1[4], w2[4], w3[4], at4[4], xr[4], acc[4];
#pragma unroll
        for (int i = 0; i < 4; i++) {
            w0[i]  = pack2(sWe[cb + 2 * i],      sWe[cb + 2 * i + 1]);
            w1[i]  = pack2(sWe[32 + cb + 2 * i], sWe[32 + cb + 2 * i + 1]);
            w2[i]  = pack2(sWe[64 + cb + 2 * i], sWe[64 + cb + 2 * i + 1]);
            w3[i]  = pack2(sWe[96 + cb + 2 * i], sWe[96 + cb + 2 * i + 1]);
            at4[i] = pack2(sAtt[cb + 2 * i],     sAtt[cb + 2 * i + 1]);
        }
        const ulonglong2* xlu = (const ulonglong2*)d_xl;
        const ulonglong2* xru = (const ulonglong2*)d_xr;
        {
            ulonglong2 X0 = xru[n * 8 + lane * 2];
            ulonglong2 X1 = xru[n * 8 + lane * 2 + 1];
            xr[0] = X0.x; xr[1] = X0.y; xr[2] = X1.x; xr[3] = X1.y;
        }
        float den;
        {   // self-loop (ew = 0)
            ulonglong2 A0 = xlu[n * 8 + lane * 2];
            ulonglong2 A1 = xlu[n * 8 + lane * 2 + 1];
            u64 a0 = A0.x, a1 = A0.y, a2 = A1.x, a3 = A1.y;
            u64 l0 = leaky2(add2(a0, xr[0]));
            u64 l1 = leaky2(add2(a1, xr[1]));
            u64 l2 = leaky2(add2(a2, xr[2]));
            u64 l3 = leaky2(add2(a3, xr[3]));
            u64 dd0 = fma2(l1, at4[1], mul2(l0, at4[0]));
            u64 dd1 = fma2(l3, at4[3], mul2(l2, at4[2]));
            float2 dv = unpack2(add2(dd0, dd1));
            float p = dv.x + dv.y;
            p += __shfl_xor_sync(pmask, p, 1);
            float ex = __expf(p);
            den = ex;
            u64 e2 = pack2(ex, ex);
            acc[0] = mul2(e2, a0); acc[1] = mul2(e2, a1);
            acc[2] = mul2(e2, a2); acc[3] = mul2(e2, a3);
        }
        int start = __ldg(&d_off[n]), deg = __ldg(&d_cnt[n]);
        const long long* qp = d_sep + start;
        long long qA = __ldg(&qp[0]);
        long long qB = __ldg(&qp[1]);
        long long qC = __ldg(&qp[2]);
        int s0 = (int)qA, i0 = (int)(qA >> 32);
        int s1 = (int)qB, i1 = (int)(qB >> 32);
        ulonglong2 A0a = __ldg(&xlu[s0 * 8 + lane * 2]);
        ulonglong2 A1a = __ldg(&xlu[s0 * 8 + lane * 2 + 1]);
        float4     EAa = __ldg(&eattr[i0]);
        ulonglong2 A0b = __ldg(&xlu[s1 * 8 + lane * 2]);
        ulonglong2 A1b = __ldg(&xlu[s1 * 8 + lane * 2 + 1]);
        float4     EAb = __ldg(&eattr[i1]);
        for (int j = 0; j < deg; j++) {
            u64 a0 = A0a.x, a1 = A0a.y, a2 = A1a.x, a3 = A1a.y;
            float4 ea = EAa;
            A0a = A0b; A1a = A1b; EAa = EAb;
            int sC = (int)qC, iC = (int)(qC >> 32);
            A0b = __ldg(&xlu[sC * 8 + lane * 2]);
            A1b = __ldg(&xlu[sC * 8 + lane * 2 + 1]);
            EAb = __ldg(&eattr[iC]);
            qC = __ldg(&qp[j + 3]);
            u64 eax = pack2(ea.x, ea.x), eay = pack2(ea.y, ea.y);
            u64 eaz = pack2(ea.z, ea.z), eaw = pack2(ea.w, ea.w);
            u64 m0 = fma2(eax, w0[0], fma2(eay, w1[0], fma2(eaz, w2[0], fma2(eaw, w3[0], add2(a0, xr[0])))));
            u64 m1 = fma2(eax, w0[1], fma2(eay, w1[1], fma2(eaz, w2[1], fma2(eaw, w3[1], add2(a1, xr[1])))));
            u64 m2 = fma2(eax, w0[2], fma2(eay, w1[2], fma2(eaz, w2[2], fma2(eaw, w3[2], add2(a2, xr[2])))));
            u64 m3 = fma2(eax, w0[3], fma2(eay, w1[3], fma2(eaz, w2[3], fma2(eaw, w3[3], add2(a3, xr[3])))));
            u64 dd0 = fma2(leaky2(m1), at4[1], mul2(leaky2(m0), at4[0]));
            u64 dd1 = fma2(leaky2(m3), at4[3], mul2(leaky2(m2), at4[2]));
            float2 dv = unpack2(add2(dd0, dd1));
            float pe = dv.x + dv.y;
            pe += __shfl_xor_sync(pmask, pe, 1);
            float exe = __expf(pe);
            den += exe;
            u64 e2 = pack2(exe, exe);
            acc[0] = fma2(e2, a0, acc[0]); acc[1] = fma2(e2, a1, acc[1]);
            acc[2] = fma2(e2, a2, acc[2]); acc[3] = fma2(e2, a3, acc[3]);
        }
        float inv = 1.f / den;
        u64 inv2 = pack2(inv, inv);
        u64 r0 = fma2(acc[0], inv2, pack2(sGb[cb],     sGb[cb + 1]));
        u64 r1 = fma2(acc[1], inv2, pack2(sGb[cb + 2], sGb[cb + 3]));
        u64 r2 = fma2(acc[2], inv2, pack2(sGb[cb + 4], sGb[cb + 5]));
        u64 r3 = fma2(acc[3], inv2, pack2(sGb[cb + 6], sGb[cb + 7]));
        ulonglong2 R0; R0.x = r0; R0.y = r1;
        ulonglong2 R1; R1.x = r2; R1.y = r3;
        ((ulonglong2*)d_g)[n * 8 + lane * 2]     = R0;
        ((ulonglong2*)d_g)[n * 8 + lane * 2 + 1] = R1;
        float2 v0 = unpack2(r0), v1 = unpack2(r1), v2 = unpack2(r2), v3 = unpack2(r3);
        s_loc = (v0.x + v0.y) + (v1.x + v1.y) + (v2.x + v2.y) + (v3.x + v3.y);
        q_loc = v0.x * v0.x + v0.y * v0.y + v1.x * v1.x + v1.y * v1.y
              + v2.x * v2.x + v2.y * v2.y + v3.x * v3.x + v3.y * v3.y;
    }
    blockReduceAdd2_256(s_loc, q_loc, &d_stats[0], &d_stats[1]);
}

// ------- K_tail: lin (graph_LN1+relu, @linW) -> stats -> gridbar ->
//         graph_LN2 + resid + relu -> h/out (+ next-layer transform for l=0).
__global__ void __launch_bounds__(256, 3) k_tail(
    const float* __restrict__ n1w, const float* __restrict__ n1b,
    const float* __restrict__ linW, const float* __restrict__ linb,
    const float* __restrict__ n2w, const float* __restrict__ n2b,
    const float* __restrict__ Wl, const float* __restrict__ bl,
    const float* __restrict__ Wr, const float* __restrict__ br,
    float* __restrict__ out, int N, int NBT, int layer)
{
    __shared__ alignas(16) float sLW[512];
    __shared__ alignas(16) float sWl[512], sWr[512];
    __shared__ float sn1w[32], sn1b[32], sbl[32], sbr[32];
    __shared__ float sn2w[16], sn2b[16], slb[16];
    int t = threadIdx.x, b = blockIdx.x;
    for (int i = t; i < 512; i += 256) {
        sLW[i] = linW[i];
        if (layer == 0) { sWl[i] = Wl[i]; sWr[i] = Wr[i]; }
    }
    if (t < 32)            { sn1w[t] = n1w[t];       sn1b[t] = n1b[t]; }
    else if (t < 64 && layer == 0) { sbl[t - 32] = bl[t - 32]; sbr[t - 32] = br[t - 32]; }
    if (t >= 64 && t < 80)  { sn2w[t - 64] = n2w[t - 64]; sn2b[t - 64] = n2b[t - 64]; }
    else if (t >= 80 && t < 96) { slb[t - 80] = linb[t - 80]; }
    __syncthreads();

    int n = b * 256 + t;
    u64 u[8];
    float s_loc = 0.f, q_loc = 0.f;
    if (n < N) {
        double mu1d  = d_stats[0] / (32.0 * N);
        double var1d = d_stats[1] / (32.0 * N) - mu1d * mu1d;
        float mu1  = (float)mu1d;
        float inv1 = rsqrtf((float)var1d + EPSV);
#pragma unroll
        for (int i = 0; i < 8; i++) u[i] = pack2(slb[2 * i], slb[2 * i + 1]);
        const float4* g4 = (const float4*)(d_g + n * 32);
#pragma unroll
        for (int kc = 0; kc < 4; kc++) {
            float4 ga = __ldg(&g4[kc * 2]);
            float4 gb = __ldg(&g4[kc * 2 + 1]);
            float tt[8];
            tt[0] = fmaxf((ga.x - mu1) * inv1 * sn1w[kc * 8 + 0] + sn1b[kc * 8 + 0], 0.f);
            tt[1] = fmaxf((ga.y - mu1) * inv1 * sn1w[kc * 8 + 1] + sn1b[kc * 8 + 1], 0.f);
            tt[2] = fmaxf((ga.z - mu1) * inv1 * sn1w[kc * 8 + 2] + sn1b[kc * 8 + 2], 0.f);
            tt[3] = fmaxf((ga.w - mu1) * inv1 * sn1w[kc * 8 + 3] + sn1b[kc * 8 + 3], 0.f);
            tt[4] = fmaxf((gb.x - mu1) * inv1 * sn1w[kc * 8 + 4] + sn1b[kc * 8 + 4], 0.f);
            tt[5] = fmaxf((gb.y - mu1) * inv1 * sn1w[kc * 8 + 5] + sn1b[kc * 8 + 5], 0.f);
            tt[6] = fmaxf((gb.z - mu1) * inv1 * sn1w[kc * 8 + 6] + sn1b[kc * 8 + 6], 0.f);
            tt[7] = fmaxf((gb.w - mu1) * inv1 * sn1w[kc * 8 + 7] + sn1b[kc * 8 + 7], 0.f);
#pragma unroll
            for (int kk = 0; kk < 8; kk++) {
                int k = kc * 8 + kk;
                u64 tk2 = pack2(tt[kk], tt[kk]);
                const u64* wrow = (const u64*)&sLW[k * 16];
#pragma unroll
                for (int i = 0; i < 8; i++) u[i] = fma2(tk2, wrow[i], u[i]);
            }
        }
#pragma unroll
        for (int i = 0; i < 8; i++) {
            float2 p = unpack2(u[i]);
            s_loc += p.x + p.y;
            q_loc += p.x * p.x + p.y * p.y;
        }
    }
    blockReduceAdd2_256(s_loc, q_loc, &d_stats[2], &d_stats[3]);
    gridbar(2 + layer, NBT);

    if (layer == 0 && b == 0 && t == 255) { d_stats[0] = 0.0; d_stats[1] = 0.0; }
    if (layer == 1) {   // restore zeroed counters for the next replay
        for (int i = b * 256 + t; i < N; i += NBT * 256) d_cnt[i] = 0;
        if (b < 4) d_dcnt[b * 256 + t] = 0;
    }
    if (n < N) {
        double mu2d  = d_stats[2] / (16.0 * N);
        double var2d = d_stats[3] / (16.0 * N) - mu2d * mu2d;
        float mu2  = (float)mu2d;
        float inv2 = rsqrtf((float)var2d + EPSV);
        float hn[16];
        const float4* h4 = (const float4*)(d_h + n * 16);
#pragma unroll
        for (int i = 0; i < 4; i++) {
            float4 hv = h4[i];
            float2 pa = unpack2(u[i * 2]), pb = unpack2(u[i * 2 + 1]);
            hn[i * 4 + 0] = fmaxf((pa.x - mu2) * inv2 * sn2w[i * 4 + 0] + sn2b[i * 4 + 0] + hv.x, 0.f);
            hn[i * 4 + 1] = fmaxf((pa.y - mu2) * inv2 * sn2w[i * 4 + 1] + sn2b[i * 4 + 1] + hv.y, 0.f);
            hn[i * 4 + 2] = fmaxf((pb.x - mu2) * inv2 * sn2w[i * 4 + 2] + sn2b[i * 4 + 2] + hv.z, 0.f);
            hn[i * 4 + 3] = fmaxf((pb.y - mu2) * inv2 * sn2w[i * 4 + 3] + sn2b[i * 4 + 3] + hv.w, 0.f);
        }
        float4* o4 = (float4*)(out + n * 16);
#pragma unroll
        for (int i = 0; i < 4; i++) {
            float4 ov = o4[i];
            ov.x = fmaxf(ov.x, hn[i * 4 + 0]);
            ov.y = fmaxf(ov.y, hn[i * 4 + 1]);
            ov.z = fmaxf(ov.z, hn[i * 4 + 2]);
            ov.w = fmaxf(ov.w, hn[i * 4 + 3]);
            o4[i] = ov;
        }
        if (layer == 0) {
            float4* hw = (float4*)(d_h + n * 16);
#pragma unroll
            for (int i = 0; i < 4; i++)
                hw[i] = make_float4(hn[i * 4], hn[i * 4 + 1], hn[i * 4 + 2], hn[i * 4 + 3]);
#pragma unroll
            for (int half = 0; half < 2; half++) {
                u64 xa[8], ra[8];
#pragma unroll
                for (int i = 0; i < 8; i++) {
                    xa[i] = pack2(sbl[half * 16 + 2 * i], sbl[half * 16 + 2 * i + 1]);
                    ra[i] = pack2(sbr[half * 16 + 2 * i], sbr[half * 16 + 2 * i + 1]);
                }
#pragma unroll
                for (int k = 0; k < 16; k++) {
                    u64 hk2 = pack2(hn[k], hn[k]);
                    const u64* wl = (const u64*)&sWl[k * 32 + half * 16];
                    const u64* wr = (const u64*)&sWr[k * 32 + half * 16];
#pragma unroll
                    for (int i = 0; i < 8; i++) {
                        xa[i] = fma2(hk2, wl[i], xa[i]);
                        ra[i] = fma2(hk2, wr[i], ra[i]);
                    }
                }
                ulonglong2* xo = (ulonglong2*)(d_xl + n * 32 + half * 16);
                ulonglong2* ro = (ulonglong2*)(d_xr + n * 32 + half * 16);
#pragma unroll
                for (int i = 0; i < 4; i++) {
                    ulonglong2 X; X.x = xa[2 * i]; X.y = xa[2 * i + 1]; xo[i] = X;
                    ulonglong2 R; R.x = ra[2 * i]; R.y = ra[2 * i + 1]; ro[i] = R;
                }
            }
        }
    }
}

// ---------------- launch ----------------
extern "C" void kernel_launch(void* const* d_in, const int* in_sizes, int n_in,
                              void* d_out, int out_size)
{
    const float* x     = (const float*)d_in[0];
    const int*   ei32  = (const int*)d_in[1];
    const float* eattr = (const float*)d_in[2];
    const float* embW  = (const float*)d_in[3];
    const float* embB  = (const float*)d_in[4];
    const float* ln0w  = (const float*)d_in[5];
    const float* ln0b  = (const float*)d_in[6];
    const float* Wl    = (const float*)d_in[7];
    const float* bl    = (const float*)d_in[8];
    const float* Wr    = (const float*)d_in[9];
    const float* br    = (const float*)d_in[10];
    const float* We    = (const float*)d_in[11];
    const float* att   = (const float*)d_in[12];
    const float* gatb  = (const float*)d_in[13];
    const float* n1w   = (const float*)d_in[14];
    const float* n1b   = (const float*)d_in[15];
    const float* linW  = (const float*)d_in[16];
    const float* linb  = (const float*)d_in[17];
    const float* n2w   = (const float*)d_in[18];
    const float* n2b   = (const float*)d_in[19];
    float* out = (float*)d_out;

    int N   = in_sizes[0] / 128;
    int E   = in_sizes[2] / 4;           // edge_attr is (E, 4)
    int NB  = (N + PB - 1) / PB;         // 196 (co-resident)
    int NBT = (N + 255) / 256;           // 391 <= 444 co-resident
    int nbe = (N + 31) / 32;

    // one-time stream/event setup (host objects only; no device memory)
    static cudaStream_t s2 = 0;
    static cudaEvent_t evFork = 0, evJoin = 0;
    if (s2 == 0) {
        cudaStreamCreateWithFlags(&s2, cudaStreamNonBlocking);
        cudaEventCreateWithFlags(&evFork, cudaEventDisableTiming);
        cudaEventCreateWithFlags(&evJoin, cudaEventDisableTiming);
    }

    // fork: embed (x -> h, xl, xr) runs concurrently with hist->scan->scatter
    cudaEventRecord(evFork, 0);
    cudaStreamWaitEvent(s2, evFork, 0);
    k_embed<<<nbe, 256, 0, s2>>>(x, embW, embB, ln0w, ln0b,
                                 Wl, bl, Wr, br, out, N);

    k_hist   <<<(E + 255) / 256, 256>>>(ei32, E, N);
    k_scan   <<<NB, PB>>>(N, NB);
    k_scatter<<<(E + 255) / 256, 256>>>(E);

    // join: edge layer 0 needs both chains complete
    cudaEventRecord(evJoin, s2);
    cudaStreamWaitEvent(0, evJoin, 0);

    for (int l = 0; l < 2; l++) {
        k_edge_csr<<<(N * 4 + 255) / 256, 256>>>((const float4*)eattr,
                                                 We + l * 128, att + l * 32,
                                                 gatb + l * 32, N, l == 1);
        k_tail<<<NBT, 256>>>(n1w + l * 32, n1b + l * 32,
                             linW + l * 512, linb + l * 16,
                             n2w + l * 16, n2b + l * 16,
                             Wl + 512, bl + 32, Wr + 512, br + 32,
                             out, N, NBT, l);
    }
}